// round 2
// baseline (speedup 1.0000x reference)
#include <cuda_runtime.h>
#include <math.h>

#define NNODES 100000
#define NEDGES 1600000
#define NB 16
#define HID 64
#define OUTD 128

// Scratch for segment_sum accumulator (static device global: no runtime allocs)
__device__ float g_agg[(size_t)NNODES * HID];

// ---------------------------------------------------------------------------
// Zero the aggregation buffer (float4 vectorized)
// ---------------------------------------------------------------------------
__global__ void zero_agg_kernel() {
    size_t i = (size_t)blockIdx.x * blockDim.x + threadIdx.x;
    size_t n4 = (size_t)NNODES * HID / 4;
    if (i < n4) reinterpret_cast<float4*>(g_agg)[i] = make_float4(0.f, 0.f, 0.f, 0.f);
}

__device__ __forceinline__ float silu_f(float x) {
    // x * sigmoid(x); __expf/__fdividef accurate to a few ulp, fine vs 1e-3 tol.
    return __fdividef(x, 1.0f + __expf(-x));
}

// Spherical harmonics constants
#define SH_C0 0.28209479177387814f  // 1/sqrt(4pi)
#define SH_C1 0.4886025119029199f   // sqrt(3/(4pi))
#define SH_C2 1.0925484305920792f   // sqrt(15/(4pi))
#define SH_C3 0.31539156525252005f  // sqrt(5/(16pi))
#define SH_C4 0.5462742152960396f   // sqrt(15/(16pi))

// ---------------------------------------------------------------------------
// Edge kernel: thread-per-edge.
//   feat(32) = [rbf(d_ij), sh(u_ij)@sh_w + sh_b]
//   pf(64)   = silu(feat@W1 + b1) @ W2 + b2
//   atomicAdd into g_agg[src]
// Weights staged in SMEM: W1 transposed so a hidden-column is contiguous
// (float4 broadcast LDS), W2 row-major.
// ---------------------------------------------------------------------------
__global__ __launch_bounds__(128) void edge_kernel(
    const float* __restrict__ pos,
    const int*   __restrict__ ei,     // [2, NEDGES]: row0=src, row1=dst
    const float* __restrict__ rbf_c,
    const float* __restrict__ rbf_w,
    const float* __restrict__ sh_w,   // [9,16]
    const float* __restrict__ sh_b,
    const float* __restrict__ w1,     // [32,64]
    const float* __restrict__ b1,
    const float* __restrict__ w2,     // [64,64]
    const float* __restrict__ b2)
{
    __shared__ float s_w1t[HID][32];      // [j][k] = w1[k][j]
    __shared__ float s_w2[HID][HID];      // row j contiguous
    __shared__ float s_b1[HID];
    __shared__ float s_b2[HID];
    __shared__ float s_c[NB], s_wd[NB], s_shb[NB];
    __shared__ float s_shw[9 * NB];

    const int tid = threadIdx.x;
    for (int i = tid; i < 32 * HID; i += blockDim.x) {
        int k = i >> 6, j = i & 63;       // w1 row k, col j
        s_w1t[j][k] = w1[i];
    }
    for (int i = tid; i < HID * HID; i += blockDim.x)
        s_w2[i >> 6][i & 63] = w2[i];
    if (tid < HID) { s_b1[tid] = b1[tid]; s_b2[tid] = b2[tid]; }
    for (int i = tid; i < 9 * NB; i += blockDim.x) s_shw[i] = sh_w[i];
    if (tid < NB) { s_c[tid] = rbf_c[tid]; s_wd[tid] = rbf_w[tid]; s_shb[tid] = sh_b[tid]; }
    __syncthreads();

    const int e = blockIdx.x * blockDim.x + tid;
    if (e >= NEDGES) return;

    const int s = ei[e];
    const int d = ei[NEDGES + e];

    const float rx = pos[3 * d + 0] - pos[3 * s + 0];
    const float ry = pos[3 * d + 1] - pos[3 * s + 1];
    const float rz = pos[3 * d + 2] - pos[3 * s + 2];
    float dist = sqrtf(rx * rx + ry * ry + rz * rz);
    dist = fmaxf(dist, 1e-6f);
    const float inv = __fdividef(1.0f, dist);
    const float ux = rx * inv, uy = ry * inv, uz = rz * inv;

    float feat[32];
#pragma unroll
    for (int k = 0; k < NB; k++) {
        const float t = dist - s_c[k];
        feat[k] = __expf(-fabsf(s_wd[k]) * t * t);
    }
    float sh[9];
    sh[0] = SH_C0;
    sh[1] = SH_C1 * uy;
    sh[2] = SH_C1 * uz;
    sh[3] = SH_C1 * ux;
    sh[4] = SH_C2 * ux * uy;
    sh[5] = SH_C2 * uy * uz;
    sh[6] = SH_C3 * (2.0f * uz * uz - ux * ux - uy * uy);
    sh[7] = SH_C2 * ux * uz;
    sh[8] = SH_C4 * (ux * ux - uy * uy);
#pragma unroll
    for (int k = 0; k < NB; k++) {
        float a = s_shb[k];
#pragma unroll
        for (int j = 0; j < 9; j++) a += sh[j] * s_shw[j * NB + k];
        feat[NB + k] = a;
    }

    // Fused two-layer MLP: pf[k] = b2[k] + sum_j silu(feat.W1[:,j]+b1[j]) * W2[j][k]
    float pf[HID];
#pragma unroll
    for (int k = 0; k < HID; k++) pf[k] = s_b2[k];

#pragma unroll 8
    for (int j = 0; j < HID; j++) {
        float a = s_b1[j];
        const float4* wr = reinterpret_cast<const float4*>(&s_w1t[j][0]);
#pragma unroll
        for (int k = 0; k < 8; k++) {
            const float4 w = wr[k];
            a += feat[4 * k + 0] * w.x + feat[4 * k + 1] * w.y
               + feat[4 * k + 2] * w.z + feat[4 * k + 3] * w.w;
        }
        a = silu_f(a);
        const float4* w2r = reinterpret_cast<const float4*>(&s_w2[j][0]);
#pragma unroll
        for (int k = 0; k < 16; k++) {
            const float4 w = w2r[k];
            pf[4 * k + 0] += a * w.x;
            pf[4 * k + 1] += a * w.y;
            pf[4 * k + 2] += a * w.z;
            pf[4 * k + 3] += a * w.w;
        }
    }

    float* ap = &g_agg[(size_t)s * HID];
#pragma unroll
    for (int k = 0; k < HID; k++) atomicAdd(ap + k, pf[k]);
}

// ---------------------------------------------------------------------------
// Node kernel: warp-per-node.
//   zn_f(64) = silu([rbf(d_izn), sh(u_izn)@sh_w+sh_b] @ zn_w + zn_b)
//   h(128)   = [agg, zn_f] @ np_w + np_b ; LayerNorm ; SiLU
// Input vector lives in registers (4 per lane), broadcast via shuffles;
// np_w read as float4 LDG (64KB, L1-resident broadcast).
// ---------------------------------------------------------------------------
__global__ __launch_bounds__(256) void node_kernel(
    const float* __restrict__ pos,
    const float* __restrict__ zinc,
    const float* __restrict__ rbf_c,
    const float* __restrict__ rbf_w,
    const float* __restrict__ sh_w,
    const float* __restrict__ sh_b,
    const float* __restrict__ zn_w,   // [32,64]
    const float* __restrict__ zn_b,
    const float* __restrict__ np_w,   // [128,128]
    const float* __restrict__ np_b,
    const float* __restrict__ ln_g,
    const float* __restrict__ ln_b,
    float* __restrict__ out)
{
    const int gwarp = (blockIdx.x * blockDim.x + threadIdx.x) >> 5;
    const int lane  = threadIdx.x & 31;
    if (gwarp >= NNODES) return;
    const int node = gwarp;

    const float rx = pos[3 * node + 0] - zinc[0];
    const float ry = pos[3 * node + 1] - zinc[1];
    const float rz = pos[3 * node + 2] - zinc[2];
    float dist = sqrtf(rx * rx + ry * ry + rz * rz);
    dist = fmaxf(dist, 1e-6f);
    const float inv = __fdividef(1.0f, dist);
    const float ux = rx * inv, uy = ry * inv, uz = rz * inv;

    float sh[9];
    sh[0] = SH_C0;
    sh[1] = SH_C1 * uy;
    sh[2] = SH_C1 * uz;
    sh[3] = SH_C1 * ux;
    sh[4] = SH_C2 * ux * uy;
    sh[5] = SH_C2 * uy * uz;
    sh[6] = SH_C3 * (2.0f * uz * uz - ux * ux - uy * uy);
    sh[7] = SH_C2 * ux * uz;
    sh[8] = SH_C4 * (ux * ux - uy * uy);

    // zfeat element `lane`: lanes 0..15 = rbf, lanes 16..31 = sh projection
    float zf;
    if (lane < NB) {
        const float t = dist - __ldg(&rbf_c[lane]);
        zf = __expf(-fabsf(__ldg(&rbf_w[lane])) * t * t);
    } else {
        const int k = lane - NB;
        float a = __ldg(&sh_b[k]);
#pragma unroll
        for (int j = 0; j < 9; j++) a += sh[j] * __ldg(&sh_w[j * NB + k]);
        zf = a;
    }

    // zinc branch hidden layer: lane computes hidden dims lane and lane+32
    float h0 = __ldg(&zn_b[lane]);
    float h1 = __ldg(&zn_b[lane + 32]);
#pragma unroll
    for (int k = 0; k < 32; k++) {
        const float v = __shfl_sync(0xffffffffu, zf, k);
        h0 += v * __ldg(&zn_w[k * HID + lane]);
        h1 += v * __ldg(&zn_w[k * HID + 32 + lane]);
    }
    h0 = silu_f(h0);
    h1 = silu_f(h1);

    // input vector: inp[k] (k<64: agg, k>=64: zn_f), distributed 4/lane
    float ir[4];
    ir[0] = g_agg[(size_t)node * HID + lane];
    ir[1] = g_agg[(size_t)node * HID + 32 + lane];
    ir[2] = h0;
    ir[3] = h1;

    // out projection: lane owns output cols 4*lane .. 4*lane+3
    float4 o = __ldg(reinterpret_cast<const float4*>(&np_b[4 * lane]));
#pragma unroll
    for (int r = 0; r < 4; r++) {
#pragma unroll
        for (int k = 0; k < 32; k++) {
            const float v = __shfl_sync(0xffffffffu, ir[r], k);
            const float4 w = __ldg(reinterpret_cast<const float4*>(
                &np_w[(size_t)(r * 32 + k) * OUTD + 4 * lane]));
            o.x += v * w.x; o.y += v * w.y; o.z += v * w.z; o.w += v * w.w;
        }
    }

    // LayerNorm over 128 (two-pass for numerical safety)
    float sum = o.x + o.y + o.z + o.w;
#pragma unroll
    for (int off = 16; off; off >>= 1) sum += __shfl_xor_sync(0xffffffffu, sum, off);
    const float mu = sum * (1.0f / 128.0f);
    const float dx = o.x - mu, dy = o.y - mu, dz = o.z - mu, dw = o.w - mu;
    float sq = dx * dx + dy * dy + dz * dz + dw * dw;
#pragma unroll
    for (int off = 16; off; off >>= 1) sq += __shfl_xor_sync(0xffffffffu, sq, off);
    const float rs = rsqrtf(sq * (1.0f / 128.0f) + 1e-5f);

    const float4 g = __ldg(reinterpret_cast<const float4*>(&ln_g[4 * lane]));
    const float4 b = __ldg(reinterpret_cast<const float4*>(&ln_b[4 * lane]));
    float4 res;
    res.x = silu_f(dx * rs * g.x + b.x);
    res.y = silu_f(dy * rs * g.y + b.y);
    res.z = silu_f(dz * rs * g.z + b.z);
    res.w = silu_f(dw * rs * g.w + b.w);
    *reinterpret_cast<float4*>(&out[(size_t)node * OUTD + 4 * lane]) = res;
}

// ---------------------------------------------------------------------------
extern "C" void kernel_launch(void* const* d_in, const int* in_sizes, int n_in,
                              void* d_out, int out_size) {
    const float* pos    = (const float*)d_in[0];
    const float* zinc   = (const float*)d_in[1];
    const int*   ei     = (const int*)  d_in[2];
    const float* rbf_c  = (const float*)d_in[3];
    const float* rbf_w  = (const float*)d_in[4];
    const float* sh_w   = (const float*)d_in[5];
    const float* sh_b   = (const float*)d_in[6];
    const float* pm_w1  = (const float*)d_in[7];
    const float* pm_b1  = (const float*)d_in[8];
    const float* pm_w2  = (const float*)d_in[9];
    const float* pm_b2  = (const float*)d_in[10];
    const float* zn_w   = (const float*)d_in[11];
    const float* zn_b   = (const float*)d_in[12];
    const float* np_w   = (const float*)d_in[13];
    const float* np_b   = (const float*)d_in[14];
    const float* ln_g   = (const float*)d_in[15];
    const float* ln_b   = (const float*)d_in[16];
    float* out = (float*)d_out;

    // 1) zero aggregation buffer: 1.6M float4s
    zero_agg_kernel<<<(NNODES * HID / 4 + 255) / 256, 256>>>();

    // 2) edge MLP + scatter-add
    edge_kernel<<<(NEDGES + 127) / 128, 128>>>(
        pos, ei, rbf_c, rbf_w, sh_w, sh_b, pm_w1, pm_b1, pm_w2, pm_b2);

    // 3) per-node projection + LN + SiLU  (8 warps/block, exact division)
    node_kernel<<<NNODES / 8, 256>>>(
        pos, zinc, rbf_c, rbf_w, sh_w, sh_b, zn_w, zn_b, np_w, np_b,
        ln_g, ln_b, out);
}

// round 3
// speedup vs baseline: 1.3617x; 1.3617x over previous
#include <cuda_runtime.h>
#include <math.h>

#define NNODES 100000
#define NEDGES 1600000
#define NB 16
#define HID 64
#define OUTD 128

typedef unsigned long long ull;

// Scratch for segment_sum accumulator (static device global: no runtime allocs)
__device__ float g_agg[(size_t)NNODES * HID];

// ---------------------------------------------------------------------------
// f32x2 packed-math helpers (sm_10x)
// ---------------------------------------------------------------------------
__device__ __forceinline__ ull pack2(float lo, float hi) {
    ull r; asm("mov.b64 %0, {%1, %2};" : "=l"(r) : "f"(lo), "f"(hi)); return r;
}
__device__ __forceinline__ void unpack2(ull v, float& lo, float& hi) {
    asm("mov.b64 {%0, %1}, %2;" : "=f"(lo), "=f"(hi) : "l"(v));
}
__device__ __forceinline__ ull fma2(ull a, ull b, ull c) {
    ull r; asm("fma.rn.f32x2 %0, %1, %2, %3;" : "=l"(r) : "l"(a), "l"(b), "l"(c));
    return r;
}

__device__ __forceinline__ float silu_f(float x) {
    return __fdividef(x, 1.0f + __expf(-x));
}

// Spherical harmonics constants
#define SH_C0 0.28209479177387814f
#define SH_C1 0.4886025119029199f
#define SH_C2 1.0925484305920792f
#define SH_C3 0.31539156525252005f
#define SH_C4 0.5462742152960396f

// ---------------------------------------------------------------------------
__global__ void zero_agg_kernel() {
    size_t i = (size_t)blockIdx.x * blockDim.x + threadIdx.x;
    size_t n4 = (size_t)NNODES * HID / 4;
    if (i < n4) reinterpret_cast<float4*>(g_agg)[i] = make_float4(0.f, 0.f, 0.f, 0.f);
}

// ---------------------------------------------------------------------------
// Edge kernel: thread-per-edge, f32x2 packed MLP, vectorized red.v4 scatter.
// ---------------------------------------------------------------------------
__global__ __launch_bounds__(128) void edge_kernel(
    const float* __restrict__ pos,
    const int*   __restrict__ ei,     // [2, NEDGES]
    const float* __restrict__ rbf_c,
    const float* __restrict__ rbf_w,
    const float* __restrict__ sh_w,   // [9,16]
    const float* __restrict__ sh_b,
    const float* __restrict__ w1,     // [32,64]
    const float* __restrict__ b1,
    const float* __restrict__ w2,     // [64,64]
    const float* __restrict__ b2)
{
    // Packed weight staging:
    //  s_w1p[j][k] = {w1[2k][j], w1[2k+1][j]}   (column j of W1, packed along input dim)
    //  s_w2p[j][k] = {w2[j][2k], w2[j][2k+1]}   (row j of W2, packed along output dim)
    __shared__ ull   s_w1p[HID][16];
    __shared__ ull   s_w2p[HID][32];
    __shared__ ull   s_b2p[32];
    __shared__ float s_b1[HID];
    __shared__ float s_c[NB], s_wd[NB], s_shb[NB];
    __shared__ float s_shw[9 * NB];

    const int tid = threadIdx.x;
    for (int i = tid; i < HID * 16; i += blockDim.x) {
        int j = i >> 4, k = i & 15;
        s_w1p[j][k] = pack2(w1[(2 * k) * HID + j], w1[(2 * k + 1) * HID + j]);
    }
    {
        const ull* w2p = reinterpret_cast<const ull*>(w2);
        for (int i = tid; i < HID * 32; i += blockDim.x)
            s_w2p[i >> 5][i & 31] = w2p[i];
    }
    if (tid < 32) s_b2p[tid] = reinterpret_cast<const ull*>(b2)[tid];
    if (tid < HID) s_b1[tid] = b1[tid];
    for (int i = tid; i < 9 * NB; i += blockDim.x) s_shw[i] = sh_w[i];
    if (tid < NB) { s_c[tid] = rbf_c[tid]; s_wd[tid] = rbf_w[tid]; s_shb[tid] = sh_b[tid]; }
    __syncthreads();

    const int e = blockIdx.x * blockDim.x + tid;
    if (e >= NEDGES) return;

    const int s = ei[e];
    const int d = ei[NEDGES + e];

    const float rx = pos[3 * d + 0] - pos[3 * s + 0];
    const float ry = pos[3 * d + 1] - pos[3 * s + 1];
    const float rz = pos[3 * d + 2] - pos[3 * s + 2];
    float dist = sqrtf(rx * rx + ry * ry + rz * rz);
    dist = fmaxf(dist, 1e-6f);
    const float inv = __fdividef(1.0f, dist);
    const float ux = rx * inv, uy = ry * inv, uz = rz * inv;

    float feat[32];
#pragma unroll
    for (int k = 0; k < NB; k++) {
        const float t = dist - s_c[k];
        feat[k] = __expf(-fabsf(s_wd[k]) * t * t);
    }
    float sh[9];
    sh[0] = SH_C0;
    sh[1] = SH_C1 * uy;
    sh[2] = SH_C1 * uz;
    sh[3] = SH_C1 * ux;
    sh[4] = SH_C2 * ux * uy;
    sh[5] = SH_C2 * uy * uz;
    sh[6] = SH_C3 * (2.0f * uz * uz - ux * ux - uy * uy);
    sh[7] = SH_C2 * ux * uz;
    sh[8] = SH_C4 * (ux * ux - uy * uy);
#pragma unroll
    for (int k = 0; k < NB; k++) {
        float a = s_shb[k];
#pragma unroll
        for (int j = 0; j < 9; j++) a += sh[j] * s_shw[j * NB + k];
        feat[NB + k] = a;
    }

    // Pack feature vector into 16 f32x2 regs
    ull feat2[16];
#pragma unroll
    for (int k = 0; k < 16; k++) feat2[k] = pack2(feat[2 * k], feat[2 * k + 1]);

    // pf (64) packed into 32 f32x2 accumulators, init with b2
    ull pf2[32];
#pragma unroll
    for (int k = 0; k < 32; k++) pf2[k] = s_b2p[k];

#pragma unroll 4
    for (int j = 0; j < HID; j++) {
        // a = feat . W1[:,j]  via packed pairs, then horizontal add
        ull acc2 = 0ull;  // {0.0f, 0.0f}
#pragma unroll
        for (int k = 0; k < 16; k++) acc2 = fma2(feat2[k], s_w1p[j][k], acc2);
        float alo, ahi; unpack2(acc2, alo, ahi);
        float a = silu_f(alo + ahi + s_b1[j]);
        const ull aa = pack2(a, a);
#pragma unroll
        for (int k = 0; k < 32; k++) pf2[k] = fma2(aa, s_w2p[j][k], pf2[k]);
    }

    // Vectorized scatter: 16 x red.global.add.v4.f32
    float* ap = &g_agg[(size_t)s * HID];
#pragma unroll
    for (int k = 0; k < 16; k++) {
        float x, y, z, w;
        unpack2(pf2[2 * k], x, y);
        unpack2(pf2[2 * k + 1], z, w);
        asm volatile("red.global.add.v4.f32 [%0], {%1, %2, %3, %4};"
                     :: "l"(ap + 4 * k), "f"(x), "f"(y), "f"(z), "f"(w)
                     : "memory");
    }
}

// ---------------------------------------------------------------------------
// Node kernel: warp-per-node, f32x2 packed projection.
// ---------------------------------------------------------------------------
__global__ __launch_bounds__(256) void node_kernel(
    const float* __restrict__ pos,
    const float* __restrict__ zinc,
    const float* __restrict__ rbf_c,
    const float* __restrict__ rbf_w,
    const float* __restrict__ sh_w,
    const float* __restrict__ sh_b,
    const float* __restrict__ zn_w,   // [32,64]
    const float* __restrict__ zn_b,
    const float* __restrict__ np_w,   // [128,128]
    const float* __restrict__ np_b,
    const float* __restrict__ ln_g,
    const float* __restrict__ ln_b,
    float* __restrict__ out)
{
    const int gwarp = (blockIdx.x * blockDim.x + threadIdx.x) >> 5;
    const int lane  = threadIdx.x & 31;
    if (gwarp >= NNODES) return;
    const int node = gwarp;

    const float rx = pos[3 * node + 0] - zinc[0];
    const float ry = pos[3 * node + 1] - zinc[1];
    const float rz = pos[3 * node + 2] - zinc[2];
    float dist = sqrtf(rx * rx + ry * ry + rz * rz);
    dist = fmaxf(dist, 1e-6f);
    const float inv = __fdividef(1.0f, dist);
    const float ux = rx * inv, uy = ry * inv, uz = rz * inv;

    float sh[9];
    sh[0] = SH_C0;
    sh[1] = SH_C1 * uy;
    sh[2] = SH_C1 * uz;
    sh[3] = SH_C1 * ux;
    sh[4] = SH_C2 * ux * uy;
    sh[5] = SH_C2 * uy * uz;
    sh[6] = SH_C3 * (2.0f * uz * uz - ux * ux - uy * uy);
    sh[7] = SH_C2 * ux * uz;
    sh[8] = SH_C4 * (ux * ux - uy * uy);

    float zf;
    if (lane < NB) {
        const float t = dist - __ldg(&rbf_c[lane]);
        zf = __expf(-fabsf(__ldg(&rbf_w[lane])) * t * t);
    } else {
        const int k = lane - NB;
        float a = __ldg(&sh_b[k]);
#pragma unroll
        for (int j = 0; j < 9; j++) a += sh[j] * __ldg(&sh_w[j * NB + k]);
        zf = a;
    }

    float h0 = __ldg(&zn_b[lane]);
    float h1 = __ldg(&zn_b[lane + 32]);
#pragma unroll
    for (int k = 0; k < 32; k++) {
        const float v = __shfl_sync(0xffffffffu, zf, k);
        h0 += v * __ldg(&zn_w[k * HID + lane]);
        h1 += v * __ldg(&zn_w[k * HID + 32 + lane]);
    }
    h0 = silu_f(h0);
    h1 = silu_f(h1);

    float ir[4];
    ir[0] = g_agg[(size_t)node * HID + lane];
    ir[1] = g_agg[(size_t)node * HID + 32 + lane];
    ir[2] = h0;
    ir[3] = h1;

    // out projection (f32x2 packed): lane owns cols 4*lane .. 4*lane+3
    const float4 bb = __ldg(reinterpret_cast<const float4*>(&np_b[4 * lane]));
    ull o01 = pack2(bb.x, bb.y);
    ull o23 = pack2(bb.z, bb.w);
#pragma unroll
    for (int r = 0; r < 4; r++) {
#pragma unroll
        for (int k = 0; k < 32; k++) {
            const float v = __shfl_sync(0xffffffffu, ir[r], k);
            const ull vv = pack2(v, v);
            const ulonglong2 w = __ldg(reinterpret_cast<const ulonglong2*>(
                &np_w[(size_t)(r * 32 + k) * OUTD + 4 * lane]));
            o01 = fma2(vv, w.x, o01);
            o23 = fma2(vv, w.y, o23);
        }
    }
    float ox, oy, oz, ow;
    unpack2(o01, ox, oy);
    unpack2(o23, oz, ow);

    float sum = ox + oy + oz + ow;
#pragma unroll
    for (int off = 16; off; off >>= 1) sum += __shfl_xor_sync(0xffffffffu, sum, off);
    const float mu = sum * (1.0f / 128.0f);
    const float dx = ox - mu, dy = oy - mu, dz = oz - mu, dw = ow - mu;
    float sq = dx * dx + dy * dy + dz * dz + dw * dw;
#pragma unroll
    for (int off = 16; off; off >>= 1) sq += __shfl_xor_sync(0xffffffffu, sq, off);
    const float rs = rsqrtf(sq * (1.0f / 128.0f) + 1e-5f);

    const float4 g = __ldg(reinterpret_cast<const float4*>(&ln_g[4 * lane]));
    const float4 b = __ldg(reinterpret_cast<const float4*>(&ln_b[4 * lane]));
    float4 res;
    res.x = silu_f(dx * rs * g.x + b.x);
    res.y = silu_f(dy * rs * g.y + b.y);
    res.z = silu_f(dz * rs * g.z + b.z);
    res.w = silu_f(dw * rs * g.w + b.w);
    *reinterpret_cast<float4*>(&out[(size_t)node * OUTD + 4 * lane]) = res;
}

// ---------------------------------------------------------------------------
extern "C" void kernel_launch(void* const* d_in, const int* in_sizes, int n_in,
                              void* d_out, int out_size) {
    const float* pos    = (const float*)d_in[0];
    const float* zinc   = (const float*)d_in[1];
    const int*   ei     = (const int*)  d_in[2];
    const float* rbf_c  = (const float*)d_in[3];
    const float* rbf_w  = (const float*)d_in[4];
    const float* sh_w   = (const float*)d_in[5];
    const float* sh_b   = (const float*)d_in[6];
    const float* pm_w1  = (const float*)d_in[7];
    const float* pm_b1  = (const float*)d_in[8];
    const float* pm_w2  = (const float*)d_in[9];
    const float* pm_b2  = (const float*)d_in[10];
    const float* zn_w   = (const float*)d_in[11];
    const float* zn_b   = (const float*)d_in[12];
    const float* np_w   = (const float*)d_in[13];
    const float* np_b   = (const float*)d_in[14];
    const float* ln_g   = (const float*)d_in[15];
    const float* ln_b   = (const float*)d_in[16];
    float* out = (float*)d_out;

    zero_agg_kernel<<<(NNODES * HID / 4 + 255) / 256, 256>>>();

    edge_kernel<<<(NEDGES + 127) / 128, 128>>>(
        pos, ei, rbf_c, rbf_w, sh_w, sh_b, pm_w1, pm_b1, pm_w2, pm_b2);

    node_kernel<<<NNODES / 8, 256>>>(
        pos, zinc, rbf_c, rbf_w, sh_w, sh_b, zn_w, zn_b, np_w, np_b,
        ln_g, ln_b, out);
}

// round 4
// speedup vs baseline: 1.5257x; 1.1204x over previous
#include <cuda_runtime.h>
#include <math.h>

#define NNODES 100000
#define NEDGES 1600000
#define NB 16
#define HID 64
#define OUTD 128
#define EHALF (NEDGES / 2)

typedef unsigned long long ull;

__device__ float g_agg[(size_t)NNODES * HID];

// ---------------------------------------------------------------------------
// f32x2 packed-math helpers (sm_10x)
// ---------------------------------------------------------------------------
__device__ __forceinline__ ull pack2(float lo, float hi) {
    ull r; asm("mov.b64 %0, {%1, %2};" : "=l"(r) : "f"(lo), "f"(hi)); return r;
}
__device__ __forceinline__ void unpack2(ull v, float& lo, float& hi) {
    asm("mov.b64 {%0, %1}, %2;" : "=f"(lo), "=f"(hi) : "l"(v));
}
__device__ __forceinline__ ull fma2(ull a, ull b, ull c) {
    ull r; asm("fma.rn.f32x2 %0, %1, %2, %3;" : "=l"(r) : "l"(a), "l"(b), "l"(c));
    return r;
}

__device__ __forceinline__ float silu_f(float x) {
    return __fdividef(x, 1.0f + __expf(-x));
}

#define SH_C0 0.28209479177387814f
#define SH_C1 0.4886025119029199f
#define SH_C2 1.0925484305920792f
#define SH_C3 0.31539156525252005f
#define SH_C4 0.5462742152960396f

// ---------------------------------------------------------------------------
__global__ void zero_agg_kernel() {
    size_t i = (size_t)blockIdx.x * blockDim.x + threadIdx.x;
    size_t n4 = (size_t)NNODES * HID / 4;
    if (i < n4) reinterpret_cast<float4*>(g_agg)[i] = make_float4(0.f, 0.f, 0.f, 0.f);
}

// ---------------------------------------------------------------------------
// Per-edge feature builder (registers only)
// ---------------------------------------------------------------------------
__device__ __forceinline__ void build_feat(
    const float* __restrict__ pos, int s, int d,
    const float* s_c, const float* s_wd, const float* s_shb, const float* s_shw,
    ull feat2[16])
{
    const float rx = pos[3 * d + 0] - pos[3 * s + 0];
    const float ry = pos[3 * d + 1] - pos[3 * s + 1];
    const float rz = pos[3 * d + 2] - pos[3 * s + 2];
    float dist = sqrtf(rx * rx + ry * ry + rz * rz);
    dist = fmaxf(dist, 1e-6f);
    const float inv = __fdividef(1.0f, dist);
    const float ux = rx * inv, uy = ry * inv, uz = rz * inv;

    float feat[32];
#pragma unroll
    for (int k = 0; k < NB; k++) {
        const float t = dist - s_c[k];
        feat[k] = __expf(-fabsf(s_wd[k]) * t * t);
    }
    float sh[9];
    sh[0] = SH_C0;
    sh[1] = SH_C1 * uy;
    sh[2] = SH_C1 * uz;
    sh[3] = SH_C1 * ux;
    sh[4] = SH_C2 * ux * uy;
    sh[5] = SH_C2 * uy * uz;
    sh[6] = SH_C3 * (2.0f * uz * uz - ux * ux - uy * uy);
    sh[7] = SH_C2 * ux * uz;
    sh[8] = SH_C4 * (ux * ux - uy * uy);
#pragma unroll
    for (int k = 0; k < NB; k++) {
        float a = s_shb[k];
#pragma unroll
        for (int j = 0; j < 9; j++) a += sh[j] * s_shw[j * NB + k];
        feat[NB + k] = a;
    }
#pragma unroll
    for (int k = 0; k < 16; k++) feat2[k] = pack2(feat[2 * k], feat[2 * k + 1]);
}

// ---------------------------------------------------------------------------
// Edge kernel: TWO edges per thread (weight reuse), f32x2 MLP, red.v4 scatter.
// ---------------------------------------------------------------------------
__global__ __launch_bounds__(128, 1) void edge_kernel(
    const float* __restrict__ pos,
    const int*   __restrict__ ei,     // [2, NEDGES]
    const float* __restrict__ rbf_c,
    const float* __restrict__ rbf_w,
    const float* __restrict__ sh_w,   // [9,16]
    const float* __restrict__ sh_b,
    const float* __restrict__ w1,     // [32,64]
    const float* __restrict__ b1,
    const float* __restrict__ w2,     // [64,64]
    const float* __restrict__ b2)
{
    __shared__ ull   s_w1p[HID][16];   // [j][k] = {w1[2k][j], w1[2k+1][j]}
    __shared__ ull   s_w2p[HID][32];   // [j][k] = {w2[j][2k], w2[j][2k+1]}
    __shared__ ull   s_b2p[32];
    __shared__ float s_b1[HID];
    __shared__ float s_c[NB], s_wd[NB], s_shb[NB];
    __shared__ float s_shw[9 * NB];

    const int tid = threadIdx.x;
    for (int i = tid; i < HID * 16; i += blockDim.x) {
        int j = i >> 4, k = i & 15;
        s_w1p[j][k] = pack2(w1[(2 * k) * HID + j], w1[(2 * k + 1) * HID + j]);
    }
    {
        const ull* w2p = reinterpret_cast<const ull*>(w2);
        for (int i = tid; i < HID * 32; i += blockDim.x)
            s_w2p[i >> 5][i & 31] = w2p[i];
    }
    if (tid < 32) s_b2p[tid] = reinterpret_cast<const ull*>(b2)[tid];
    if (tid < HID) s_b1[tid] = b1[tid];
    for (int i = tid; i < 9 * NB; i += blockDim.x) s_shw[i] = sh_w[i];
    if (tid < NB) { s_c[tid] = rbf_c[tid]; s_wd[tid] = rbf_w[tid]; s_shb[tid] = sh_b[tid]; }
    __syncthreads();

    const int e = blockIdx.x * blockDim.x + tid;   // grid covers EHALF threads
    if (e >= EHALF) return;
    const int eB = e + EHALF;

    const int sA = ei[e];
    const int dA = ei[NEDGES + e];
    const int sB = ei[eB];
    const int dB = ei[NEDGES + eB];

    ull featA[16], featB[16];
    build_feat(pos, sA, dA, s_c, s_wd, s_shb, s_shw, featA);
    build_feat(pos, sB, dB, s_c, s_wd, s_shb, s_shw, featB);

    ull pfA[32], pfB[32];
#pragma unroll
    for (int k = 0; k < 32; k++) { pfA[k] = s_b2p[k]; pfB[k] = s_b2p[k]; }

#pragma unroll 2
    for (int j = 0; j < HID; j++) {
        // W1 dot for both edges (weights loaded ONCE), 2 partial chains each
        ull a0 = 0ull, a1 = 0ull, b0 = 0ull, b1r = 0ull;
#pragma unroll
        for (int k = 0; k < 16; k += 2) {
            const ull w0 = s_w1p[j][k];
            const ull w1v = s_w1p[j][k + 1];
            a0 = fma2(featA[k],     w0,  a0);
            b0 = fma2(featB[k],     w0,  b0);
            a1 = fma2(featA[k + 1], w1v, a1);
            b1r = fma2(featB[k + 1], w1v, b1r);
        }
        float alo, ahi, blo, bhi, alo1, ahi1, blo1, bhi1;
        unpack2(a0, alo, ahi);   unpack2(a1, alo1, ahi1);
        unpack2(b0, blo, bhi);   unpack2(b1r, blo1, bhi1);
        const float bj = s_b1[j];
        const float aA = silu_f(alo + ahi + alo1 + ahi1 + bj);
        const float aB = silu_f(blo + bhi + blo1 + bhi1 + bj);
        const ull aaA = pack2(aA, aA);
        const ull aaB = pack2(aB, aB);
#pragma unroll
        for (int k = 0; k < 32; k++) {
            const ull w = s_w2p[j][k];
            pfA[k] = fma2(aaA, w, pfA[k]);
            pfB[k] = fma2(aaB, w, pfB[k]);
        }
    }

    // Vectorized scatter
    float* apA = &g_agg[(size_t)sA * HID];
#pragma unroll
    for (int k = 0; k < 16; k++) {
        float x, y, z, w;
        unpack2(pfA[2 * k], x, y);
        unpack2(pfA[2 * k + 1], z, w);
        asm volatile("red.global.add.v4.f32 [%0], {%1, %2, %3, %4};"
                     :: "l"(apA + 4 * k), "f"(x), "f"(y), "f"(z), "f"(w)
                     : "memory");
    }
    float* apB = &g_agg[(size_t)sB * HID];
#pragma unroll
    for (int k = 0; k < 16; k++) {
        float x, y, z, w;
        unpack2(pfB[2 * k], x, y);
        unpack2(pfB[2 * k + 1], z, w);
        asm volatile("red.global.add.v4.f32 [%0], {%1, %2, %3, %4};"
                     :: "l"(apB + 4 * k), "f"(x), "f"(y), "f"(z), "f"(w)
                     : "memory");
    }
}

// ---------------------------------------------------------------------------
// Node kernel: warp-per-node, f32x2 packed projection.
// ---------------------------------------------------------------------------
__global__ __launch_bounds__(256) void node_kernel(
    const float* __restrict__ pos,
    const float* __restrict__ zinc,
    const float* __restrict__ rbf_c,
    const float* __restrict__ rbf_w,
    const float* __restrict__ sh_w,
    const float* __restrict__ sh_b,
    const float* __restrict__ zn_w,   // [32,64]
    const float* __restrict__ zn_b,
    const float* __restrict__ np_w,   // [128,128]
    const float* __restrict__ np_b,
    const float* __restrict__ ln_g,
    const float* __restrict__ ln_b,
    float* __restrict__ out)
{
    const int gwarp = (blockIdx.x * blockDim.x + threadIdx.x) >> 5;
    const int lane  = threadIdx.x & 31;
    if (gwarp >= NNODES) return;
    const int node = gwarp;

    const float rx = pos[3 * node + 0] - zinc[0];
    const float ry = pos[3 * node + 1] - zinc[1];
    const float rz = pos[3 * node + 2] - zinc[2];
    float dist = sqrtf(rx * rx + ry * ry + rz * rz);
    dist = fmaxf(dist, 1e-6f);
    const float inv = __fdividef(1.0f, dist);
    const float ux = rx * inv, uy = ry * inv, uz = rz * inv;

    float sh[9];
    sh[0] = SH_C0;
    sh[1] = SH_C1 * uy;
    sh[2] = SH_C1 * uz;
    sh[3] = SH_C1 * ux;
    sh[4] = SH_C2 * ux * uy;
    sh[5] = SH_C2 * uy * uz;
    sh[6] = SH_C3 * (2.0f * uz * uz - ux * ux - uy * uy);
    sh[7] = SH_C2 * ux * uz;
    sh[8] = SH_C4 * (ux * ux - uy * uy);

    float zf;
    if (lane < NB) {
        const float t = dist - __ldg(&rbf_c[lane]);
        zf = __expf(-fabsf(__ldg(&rbf_w[lane])) * t * t);
    } else {
        const int k = lane - NB;
        float a = __ldg(&sh_b[k]);
#pragma unroll
        for (int j = 0; j < 9; j++) a += sh[j] * __ldg(&sh_w[j * NB + k]);
        zf = a;
    }

    float h0 = __ldg(&zn_b[lane]);
    float h1 = __ldg(&zn_b[lane + 32]);
#pragma unroll
    for (int k = 0; k < 32; k++) {
        const float v = __shfl_sync(0xffffffffu, zf, k);
        h0 += v * __ldg(&zn_w[k * HID + lane]);
        h1 += v * __ldg(&zn_w[k * HID + 32 + lane]);
    }
    h0 = silu_f(h0);
    h1 = silu_f(h1);

    float ir[4];
    ir[0] = g_agg[(size_t)node * HID + lane];
    ir[1] = g_agg[(size_t)node * HID + 32 + lane];
    ir[2] = h0;
    ir[3] = h1;

    const float4 bb = __ldg(reinterpret_cast<const float4*>(&np_b[4 * lane]));
    ull o01 = pack2(bb.x, bb.y);
    ull o23 = pack2(bb.z, bb.w);
#pragma unroll
    for (int r = 0; r < 4; r++) {
#pragma unroll
        for (int k = 0; k < 32; k++) {
            const float v = __shfl_sync(0xffffffffu, ir[r], k);
            const ull vv = pack2(v, v);
            const ulonglong2 w = __ldg(reinterpret_cast<const ulonglong2*>(
                &np_w[(size_t)(r * 32 + k) * OUTD + 4 * lane]));
            o01 = fma2(vv, w.x, o01);
            o23 = fma2(vv, w.y, o23);
        }
    }
    float ox, oy, oz, ow;
    unpack2(o01, ox, oy);
    unpack2(o23, oz, ow);

    float sum = ox + oy + oz + ow;
#pragma unroll
    for (int off = 16; off; off >>= 1) sum += __shfl_xor_sync(0xffffffffu, sum, off);
    const float mu = sum * (1.0f / 128.0f);
    const float dx = ox - mu, dy = oy - mu, dz = oz - mu, dw = ow - mu;
    float sq = dx * dx + dy * dy + dz * dz + dw * dw;
#pragma unroll
    for (int off = 16; off; off >>= 1) sq += __shfl_xor_sync(0xffffffffu, sq, off);
    const float rs = rsqrtf(sq * (1.0f / 128.0f) + 1e-5f);

    const float4 g = __ldg(reinterpret_cast<const float4*>(&ln_g[4 * lane]));
    const float4 b = __ldg(reinterpret_cast<const float4*>(&ln_b[4 * lane]));
    float4 res;
    res.x = silu_f(dx * rs * g.x + b.x);
    res.y = silu_f(dy * rs * g.y + b.y);
    res.z = silu_f(dz * rs * g.z + b.z);
    res.w = silu_f(dw * rs * g.w + b.w);
    *reinterpret_cast<float4*>(&out[(size_t)node * OUTD + 4 * lane]) = res;
}

// ---------------------------------------------------------------------------
extern "C" void kernel_launch(void* const* d_in, const int* in_sizes, int n_in,
                              void* d_out, int out_size) {
    const float* pos    = (const float*)d_in[0];
    const float* zinc   = (const float*)d_in[1];
    const int*   ei     = (const int*)  d_in[2];
    const float* rbf_c  = (const float*)d_in[3];
    const float* rbf_w  = (const float*)d_in[4];
    const float* sh_w   = (const float*)d_in[5];
    const float* sh_b   = (const float*)d_in[6];
    const float* pm_w1  = (const float*)d_in[7];
    const float* pm_b1  = (const float*)d_in[8];
    const float* pm_w2  = (const float*)d_in[9];
    const float* pm_b2  = (const float*)d_in[10];
    const float* zn_w   = (const float*)d_in[11];
    const float* zn_b   = (const float*)d_in[12];
    const float* np_w   = (const float*)d_in[13];
    const float* np_b   = (const float*)d_in[14];
    const float* ln_g   = (const float*)d_in[15];
    const float* ln_b   = (const float*)d_in[16];
    float* out = (float*)d_out;

    zero_agg_kernel<<<(NNODES * HID / 4 + 255) / 256, 256>>>();

    edge_kernel<<<(EHALF + 127) / 128, 128>>>(
        pos, ei, rbf_c, rbf_w, sh_w, sh_b, pm_w1, pm_b1, pm_w2, pm_b2);

    node_kernel<<<NNODES / 8, 256>>>(
        pos, zinc, rbf_c, rbf_w, sh_w, sh_b, zn_w, zn_b, np_w, np_b,
        ln_g, ln_b, out);
}

// round 8
// speedup vs baseline: 2.1790x; 1.4282x over previous
#include <cuda_runtime.h>
#include <cuda_bf16.h>
#include <math.h>
#include <stdint.h>

#define NNODES 100000
#define NEDGES 1600000
#define NB 16
#define HID 64
#define OUTD 128
#define NCHUNKS (NEDGES / 32)    // 50000 warp-chunks
#define EDGE_BLOCKS 148

typedef unsigned long long ull;

__device__ float g_agg[(size_t)NNODES * HID];

// ---------------------------------------------------------------------------
// SMEM layout (bytes)
// ---------------------------------------------------------------------------
#define OFF_B1V  0                    // 64 f32
#define OFF_B2V  256                  // 64 f32
#define OFF_CON  512                  // 192 f32 (c,wd,shb,shw) -> ends 1280
#define OFF_W1T  1536                 // 64 n x 104 kslots bf16, stride 208B
#define OFF_W2T  (OFF_W1T + 64*208)   // 64 n x 200 kslots bf16, stride 400B
#define OFF_A1   (OFF_W2T + 64*400)   // 256 rows x 208B   ([Fh|Fh|Fl] K=96)
#define OFF_A2   (OFF_A1 + 256*208)   // 256 rows x 400B   ([Ph|Ph|Pl] K=192)
#define SMEM_BYTES (OFF_A2 + 256*400) // 196096

// ---------------------------------------------------------------------------
// helpers
// ---------------------------------------------------------------------------
__device__ __forceinline__ float silu_f(float x) {
    return __fdividef(x, 1.0f + __expf(-x));
}
__device__ __forceinline__ float trunc_hi(float x) {
    return __uint_as_float(__float_as_uint(x) & 0xFFFF0000u);
}
__device__ __forceinline__ unsigned short hi16(float x) {
    return (unsigned short)(__float_as_uint(x) >> 16);
}
__device__ __forceinline__ unsigned short lo_bf16(float x) {
    return __bfloat16_as_ushort(__float2bfloat16_rn(x - trunc_hi(x)));
}
// {lo_half = hi16(a), hi_half = hi16(b)}  (even col in low half)
__device__ __forceinline__ uint32_t pack_hi2(float a, float b) {
    uint32_t r;
    asm("prmt.b32 %0, %1, %2, 0x7632;"
        : "=r"(r) : "r"(__float_as_uint(a)), "r"(__float_as_uint(b)));
    return r;
}
// {lo_half = bf16(a - hi(a)), hi_half = bf16(b - hi(b))}
__device__ __forceinline__ uint32_t pack_lo2(float a, float b) {
    float la = a - trunc_hi(a), lb = b - trunc_hi(b);
    uint32_t r;
    asm("cvt.rn.bf16x2.f32 %0, %1, %2;" : "=r"(r) : "f"(lb), "f"(la));
    return r;
}
__device__ __forceinline__ void mma16816(float& d0, float& d1, float& d2, float& d3,
                                         uint32_t a0, uint32_t a1, uint32_t a2, uint32_t a3,
                                         uint32_t b0, uint32_t b1) {
    asm volatile(
        "mma.sync.aligned.m16n8k16.row.col.f32.bf16.bf16.f32 "
        "{%0,%1,%2,%3}, {%4,%5,%6,%7}, {%8,%9}, {%0,%1,%2,%3};"
        : "+f"(d0), "+f"(d1), "+f"(d2), "+f"(d3)
        : "r"(a0), "r"(a1), "r"(a2), "r"(a3), "r"(b0), "r"(b1));
}

#define SH_C0 0.28209479177387814f
#define SH_C1 0.4886025119029199f
#define SH_C2 1.0925484305920792f
#define SH_C3 0.31539156525252005f
#define SH_C4 0.5462742152960396f

// ---------------------------------------------------------------------------
__global__ void zero_agg_kernel() {
    size_t i = (size_t)blockIdx.x * blockDim.x + threadIdx.x;
    size_t n4 = (size_t)NNODES * HID / 4;
    if (i < n4) reinterpret_cast<float4*>(g_agg)[i] = make_float4(0.f, 0.f, 0.f, 0.f);
}

// ---------------------------------------------------------------------------
// Edge kernel: warp-per-32-edges, mma.sync bf16 3-term split GEMMs.
// ---------------------------------------------------------------------------
__global__ __launch_bounds__(256) void edge_kernel(
    const float* __restrict__ pos,
    const int*   __restrict__ ei,
    const float* __restrict__ rbf_c,
    const float* __restrict__ rbf_w,
    const float* __restrict__ sh_w,
    const float* __restrict__ sh_b,
    const float* __restrict__ w1,     // [32,64]
    const float* __restrict__ b1,
    const float* __restrict__ w2,     // [64,64]
    const float* __restrict__ b2)
{
    extern __shared__ char smem[];
    const int tid = threadIdx.x;
    const int wid = tid >> 5;
    const int lane = tid & 31;

    // ---- stage stacked/transposed split weights (once per block) ----
    // W1 stack rows k: [0,32)=W1h, [32,64)=W1l, [64,96)=W1h; stored [n][k]
    for (int i = tid; i < 64 * 96; i += 256) {
        const int n = i / 96, k = i % 96;
        unsigned short v;
        if (k < 32)      v = hi16(w1[k * HID + n]);
        else if (k < 64) v = lo_bf16(w1[(k - 32) * HID + n]);
        else             v = hi16(w1[(k - 64) * HID + n]);
        *reinterpret_cast<unsigned short*>(smem + OFF_W1T + n * 208 + k * 2) = v;
    }
    // W2 stack rows k: [0,64)=W2h, [64,128)=W2l, [128,192)=W2h; stored [n][k]
    for (int i = tid; i < 64 * 192; i += 256) {
        const int n = i / 192, k = i % 192;
        unsigned short v;
        if (k < 64)       v = hi16(w2[k * HID + n]);
        else if (k < 128) v = lo_bf16(w2[(k - 64) * HID + n]);
        else              v = hi16(w2[(k - 128) * HID + n]);
        *reinterpret_cast<unsigned short*>(smem + OFF_W2T + n * 400 + k * 2) = v;
    }
    float* s_b1v = reinterpret_cast<float*>(smem + OFF_B1V);
    float* s_b2v = reinterpret_cast<float*>(smem + OFF_B2V);
    float* s_con = reinterpret_cast<float*>(smem + OFF_CON);
    if (tid < HID) { s_b1v[tid] = b1[tid]; s_b2v[tid] = b2[tid]; }
    if (tid < NB) {
        s_con[tid]      = rbf_c[tid];
        s_con[16 + tid] = rbf_w[tid];
        s_con[32 + tid] = sh_b[tid];
    }
    for (int i = tid; i < 9 * NB; i += 256) s_con[48 + i] = sh_w[i];
    __syncthreads();

    const float* s_c   = s_con;
    const float* s_wd  = s_con + 16;
    const float* s_shb = s_con + 32;
    const float* s_shw = s_con + 48;

    char* A1w = smem + OFF_A1 + wid * 32 * 208;
    char* A2w = smem + OFF_A2 + wid * 32 * 400;
    char* PFw = A2w;                       // pf staging reuses this warp's A2 slice

    const int r0 = lane >> 2;              // 0..7
    const int qp = lane & 3;               // 0..3
    const int xr = (lane >> 3) & 3;        // pf-read swizzle

    for (int chunk = blockIdx.x * 8 + wid; chunk < NCHUNKS; chunk += gridDim.x * 8) {
        const int e = chunk * 32 + lane;
        const int s = ei[e];
        const int d = ei[NEDGES + e];

        // ---- feature build (fp32) ----
        const float rx = pos[3 * d + 0] - pos[3 * s + 0];
        const float ry = pos[3 * d + 1] - pos[3 * s + 1];
        const float rz = pos[3 * d + 2] - pos[3 * s + 2];
        float dist = fmaxf(sqrtf(rx * rx + ry * ry + rz * rz), 1e-6f);
        const float inv = __fdividef(1.0f, dist);
        const float ux = rx * inv, uy = ry * inv, uz = rz * inv;

        float feat[32];
#pragma unroll
        for (int k = 0; k < NB; k++) {
            const float tt = dist - s_c[k];
            feat[k] = __expf(-fabsf(s_wd[k]) * tt * tt);
        }
        {
            float sh[9];
            sh[0] = SH_C0;
            sh[1] = SH_C1 * uy;
            sh[2] = SH_C1 * uz;
            sh[3] = SH_C1 * ux;
            sh[4] = SH_C2 * ux * uy;
            sh[5] = SH_C2 * uy * uz;
            sh[6] = SH_C3 * (2.0f * uz * uz - ux * ux - uy * uy);
            sh[7] = SH_C2 * ux * uz;
            sh[8] = SH_C4 * (ux * ux - uy * uy);
#pragma unroll
            for (int k = 0; k < NB; k++) {
                float a = s_shb[k];
#pragma unroll
                for (int j = 0; j < 9; j++) a += sh[j] * s_shw[j * NB + k];
                feat[NB + k] = a;
            }
        }

        // ---- write A1 row `lane`: [Fh(0..31) | Fh(32..63) | Fl(64..95)] ----
        {
            char* row = A1w + lane * 208;
#pragma unroll
            for (int c = 0; c < 4; c++) {
                uint4 hi, lo;
                hi.x = pack_hi2(feat[8 * c + 0], feat[8 * c + 1]);
                hi.y = pack_hi2(feat[8 * c + 2], feat[8 * c + 3]);
                hi.z = pack_hi2(feat[8 * c + 4], feat[8 * c + 5]);
                hi.w = pack_hi2(feat[8 * c + 6], feat[8 * c + 7]);
                lo.x = pack_lo2(feat[8 * c + 0], feat[8 * c + 1]);
                lo.y = pack_lo2(feat[8 * c + 2], feat[8 * c + 3]);
                lo.z = pack_lo2(feat[8 * c + 4], feat[8 * c + 5]);
                lo.w = pack_lo2(feat[8 * c + 6], feat[8 * c + 7]);
                *reinterpret_cast<uint4*>(row + c * 16)       = hi;
                *reinterpret_cast<uint4*>(row + 64 + c * 16)  = hi;
                *reinterpret_cast<uint4*>(row + 128 + c * 16) = lo;
            }
        }
        __syncwarp();

        float dacc[2][8][4];
#pragma unroll
        for (int mt = 0; mt < 2; mt++)
#pragma unroll
            for (int nt = 0; nt < 8; nt++)
#pragma unroll
                for (int j = 0; j < 4; j++) dacc[mt][nt][j] = 0.0f;

        // ---- GEMM1: [32 x 96] @ [96 x 64] ----
#pragma unroll
        for (int kt = 0; kt < 6; kt++) {
            uint32_t a[2][4];
#pragma unroll
            for (int mt = 0; mt < 2; mt++) {
                const char* base = A1w + (mt * 16 + r0) * 208 + kt * 32 + qp * 4;
                a[mt][0] = *reinterpret_cast<const uint32_t*>(base);
                a[mt][1] = *reinterpret_cast<const uint32_t*>(base + 8 * 208);
                a[mt][2] = *reinterpret_cast<const uint32_t*>(base + 16);
                a[mt][3] = *reinterpret_cast<const uint32_t*>(base + 8 * 208 + 16);
            }
#pragma unroll
            for (int nt = 0; nt < 8; nt++) {
                const char* bb = smem + OFF_W1T + (nt * 8 + r0) * 208 + kt * 32 + qp * 4;
                const uint32_t b0 = *reinterpret_cast<const uint32_t*>(bb);
                const uint32_t bb1 = *reinterpret_cast<const uint32_t*>(bb + 16);
                mma16816(dacc[0][nt][0], dacc[0][nt][1], dacc[0][nt][2], dacc[0][nt][3],
                         a[0][0], a[0][1], a[0][2], a[0][3], b0, bb1);
                mma16816(dacc[1][nt][0], dacc[1][nt][1], dacc[1][nt][2], dacc[1][nt][3],
                         a[1][0], a[1][1], a[1][2], a[1][3], b0, bb1);
            }
        }

        // ---- epilogue1: bias + silu + hi/lo split -> A2 rows ----
#pragma unroll
        for (int nt = 0; nt < 8; nt++) {
            const float2 bp = *reinterpret_cast<const float2*>(s_b1v + nt * 8 + 2 * qp);
#pragma unroll
            for (int mt = 0; mt < 2; mt++) {
#pragma unroll
                for (int sdx = 0; sdx < 2; sdx++) {
                    const float p0 = silu_f(dacc[mt][nt][2 * sdx + 0] + bp.x);
                    const float p1 = silu_f(dacc[mt][nt][2 * sdx + 1] + bp.y);
                    const int rloc = mt * 16 + sdx * 8 + r0;
                    char* prow = A2w + rloc * 400;
                    const int cb = nt * 16 + qp * 4;
                    const uint32_t hi = pack_hi2(p0, p1);
                    const uint32_t lo = pack_lo2(p0, p1);
                    *reinterpret_cast<uint32_t*>(prow + cb)       = hi;
                    *reinterpret_cast<uint32_t*>(prow + 128 + cb) = hi;
                    *reinterpret_cast<uint32_t*>(prow + 256 + cb) = lo;
                }
            }
        }
        __syncwarp();

        // ---- GEMM2: [32 x 192] @ [192 x 64] ----
#pragma unroll
        for (int mt = 0; mt < 2; mt++)
#pragma unroll
            for (int nt = 0; nt < 8; nt++)
#pragma unroll
                for (int j = 0; j < 4; j++) dacc[mt][nt][j] = 0.0f;

#pragma unroll 4
        for (int kt = 0; kt < 12; kt++) {
            uint32_t a[2][4];
#pragma unroll
            for (int mt = 0; mt < 2; mt++) {
                const char* base = A2w + (mt * 16 + r0) * 400 + kt * 32 + qp * 4;
                a[mt][0] = *reinterpret_cast<const uint32_t*>(base);
                a[mt][1] = *reinterpret_cast<const uint32_t*>(base + 8 * 400);
                a[mt][2] = *reinterpret_cast<const uint32_t*>(base + 16);
                a[mt][3] = *reinterpret_cast<const uint32_t*>(base + 8 * 400 + 16);
            }
#pragma unroll
            for (int nt = 0; nt < 8; nt++) {
                const char* bb = smem + OFF_W2T + (nt * 8 + r0) * 400 + kt * 32 + qp * 4;
                const uint32_t b0 = *reinterpret_cast<const uint32_t*>(bb);
                const uint32_t bb1 = *reinterpret_cast<const uint32_t*>(bb + 16);
                mma16816(dacc[0][nt][0], dacc[0][nt][1], dacc[0][nt][2], dacc[0][nt][3],
                         a[0][0], a[0][1], a[0][2], a[0][3], b0, bb1);
                mma16816(dacc[1][nt][0], dacc[1][nt][1], dacc[1][nt][2], dacc[1][nt][3],
                         a[1][0], a[1][1], a[1][2], a[1][3], b0, bb1);
            }
        }
        __syncwarp();

        // ---- epilogue2: bias -> pf staging (swizzled) ----
#pragma unroll
        for (int nt = 0; nt < 8; nt++) {
            const float2 bp = *reinterpret_cast<const float2*>(s_b2v + nt * 8 + 2 * qp);
            const int g = (qp >> 1) + 2 * nt;          // 16B-granule of col pair
            const int gsub = (qp & 1) << 3;            // 8B offset within granule
#pragma unroll
            for (int mt = 0; mt < 2; mt++) {
#pragma unroll
                for (int sdx = 0; sdx < 2; sdx++) {
                    const int rloc = mt * 16 + sdx * 8 + r0;
                    float2 v;
                    v.x = dacc[mt][nt][2 * sdx + 0] + bp.x;
                    v.y = dacc[mt][nt][2 * sdx + 1] + bp.y;
                    const int gs = g ^ ((rloc >> 3) & 3);
                    *reinterpret_cast<float2*>(PFw + rloc * 272 + gs * 16 + gsub) = v;
                }
            }
        }
        __syncwarp();

        // ---- scatter: thread reads its own pf row, red.v4 ----
        {
            const char* myrow = PFw + lane * 272;
            float* ap = g_agg + (size_t)s * HID;
#pragma unroll
            for (int i = 0; i < 16; i++) {
                const float4 v = *reinterpret_cast<const float4*>(myrow + ((i ^ xr) << 4));
                asm volatile("red.global.add.v4.f32 [%0], {%1, %2, %3, %4};"
                             :: "l"(ap + 4 * i), "f"(v.x), "f"(v.y), "f"(v.z), "f"(v.w)
                             : "memory");
            }
        }
        __syncwarp();
    }
}

// ---------------------------------------------------------------------------
// Node kernel (unchanged from best passing version)
// ---------------------------------------------------------------------------
__device__ __forceinline__ ull pack2(float lo, float hi) {
    ull r; asm("mov.b64 %0, {%1, %2};" : "=l"(r) : "f"(lo), "f"(hi)); return r;
}
__device__ __forceinline__ void unpack2(ull v, float& lo, float& hi) {
    asm("mov.b64 {%0, %1}, %2;" : "=f"(lo), "=f"(hi) : "l"(v));
}
__device__ __forceinline__ ull fma2(ull a, ull b, ull c) {
    ull r; asm("fma.rn.f32x2 %0, %1, %2, %3;" : "=l"(r) : "l"(a), "l"(b), "l"(c));
    return r;
}

__global__ __launch_bounds__(256) void node_kernel(
    const float* __restrict__ pos,
    const float* __restrict__ zinc,
    const float* __restrict__ rbf_c,
    const float* __restrict__ rbf_w,
    const float* __restrict__ sh_w,
    const float* __restrict__ sh_b,
    const float* __restrict__ zn_w,
    const float* __restrict__ zn_b,
    const float* __restrict__ np_w,
    const float* __restrict__ np_b,
    const float* __restrict__ ln_g,
    const float* __restrict__ ln_b,
    float* __restrict__ out)
{
    const int gwarp = (blockIdx.x * blockDim.x + threadIdx.x) >> 5;
    const int lane  = threadIdx.x & 31;
    if (gwarp >= NNODES) return;
    const int node = gwarp;

    const float rx = pos[3 * node + 0] - zinc[0];
    const float ry = pos[3 * node + 1] - zinc[1];
    const float rz = pos[3 * node + 2] - zinc[2];
    float dist = fmaxf(sqrtf(rx * rx + ry * ry + rz * rz), 1e-6f);
    const float inv = __fdividef(1.0f, dist);
    const float ux = rx * inv, uy = ry * inv, uz = rz * inv;

    float sh[9];
    sh[0] = SH_C0;
    sh[1] = SH_C1 * uy;
    sh[2] = SH_C1 * uz;
    sh[3] = SH_C1 * ux;
    sh[4] = SH_C2 * ux * uy;
    sh[5] = SH_C2 * uy * uz;
    sh[6] = SH_C3 * (2.0f * uz * uz - ux * ux - uy * uy);
    sh[7] = SH_C2 * ux * uz;
    sh[8] = SH_C4 * (ux * ux - uy * uy);

    float zf;
    if (lane < NB) {
        const float t = dist - __ldg(&rbf_c[lane]);
        zf = __expf(-fabsf(__ldg(&rbf_w[lane])) * t * t);
    } else {
        const int k = lane - NB;
        float a = __ldg(&sh_b[k]);
#pragma unroll
        for (int j = 0; j < 9; j++) a += sh[j] * __ldg(&sh_w[j * NB + k]);
        zf = a;
    }

    float h0 = __ldg(&zn_b[lane]);
    float h1 = __ldg(&zn_b[lane + 32]);
#pragma unroll
    for (int k = 0; k < 32; k++) {
        const float v = __shfl_sync(0xffffffffu, zf, k);
        h0 += v * __ldg(&zn_w[k * HID + lane]);
        h1 += v * __ldg(&zn_w[k * HID + 32 + lane]);
    }
    h0 = silu_f(h0);
    h1 = silu_f(h1);

    float ir[4];
    ir[0] = g_agg[(size_t)node * HID + lane];
    ir[1] = g_agg[(size_t)node * HID + 32 + lane];
    ir[2] = h0;
    ir[3] = h1;

    const float4 bb = __ldg(reinterpret_cast<const float4*>(&np_b[4 * lane]));
    ull o01 = pack2(bb.x, bb.y);
    ull o23 = pack2(bb.z, bb.w);
#pragma unroll
    for (int r = 0; r < 4; r++) {
#pragma unroll
        for (int k = 0; k < 32; k++) {
            const float v = __shfl_sync(0xffffffffu, ir[r], k);
            const ull vv = pack2(v, v);
            const ulonglong2 w = __ldg(reinterpret_cast<const ulonglong2*>(
                &np_w[(size_t)(r * 32 + k) * OUTD + 4 * lane]));
            o01 = fma2(vv, w.x, o01);
            o23 = fma2(vv, w.y, o23);
        }
    }
    float ox, oy, oz, ow;
    unpack2(o01, ox, oy);
    unpack2(o23, oz, ow);

    float sum = ox + oy + oz + ow;
#pragma unroll
    for (int off = 16; off; off >>= 1) sum += __shfl_xor_sync(0xffffffffu, sum, off);
    const float mu = sum * (1.0f / 128.0f);
    const float dx = ox - mu, dy = oy - mu, dz = oz - mu, dw = ow - mu;
    float sq = dx * dx + dy * dy + dz * dz + dw * dw;
#pragma unroll
    for (int off = 16; off; off >>= 1) sq += __shfl_xor_sync(0xffffffffu, sq, off);
    const float rs = rsqrtf(sq * (1.0f / 128.0f) + 1e-5f);

    const float4 g = __ldg(reinterpret_cast<const float4*>(&ln_g[4 * lane]));
    const float4 b = __ldg(reinterpret_cast<const float4*>(&ln_b[4 * lane]));
    float4 res;
    res.x = silu_f(dx * rs * g.x + b.x);
    res.y = silu_f(dy * rs * g.y + b.y);
    res.z = silu_f(dz * rs * g.z + b.z);
    res.w = silu_f(dw * rs * g.w + b.w);
    *reinterpret_cast<float4*>(&out[(size_t)node * OUTD + 4 * lane]) = res;
}

// ---------------------------------------------------------------------------
extern "C" void kernel_launch(void* const* d_in, const int* in_sizes, int n_in,
                              void* d_out, int out_size) {
    const float* pos    = (const float*)d_in[0];
    const float* zinc   = (const float*)d_in[1];
    const int*   ei     = (const int*)  d_in[2];
    const float* rbf_c  = (const float*)d_in[3];
    const float* rbf_w  = (const float*)d_in[4];
    const float* sh_w   = (const float*)d_in[5];
    const float* sh_b   = (const float*)d_in[6];
    const float* pm_w1  = (const float*)d_in[7];
    const float* pm_b1  = (const float*)d_in[8];
    const float* pm_w2  = (const float*)d_in[9];
    const float* pm_b2  = (const float*)d_in[10];
    const float* zn_w   = (const float*)d_in[11];
    const float* zn_b   = (const float*)d_in[12];
    const float* np_w   = (const float*)d_in[13];
    const float* np_b   = (const float*)d_in[14];
    const float* ln_g   = (const float*)d_in[15];
    const float* ln_b   = (const float*)d_in[16];
    float* out = (float*)d_out;

    static int smem_set = 0;
    if (!smem_set) {
        cudaFuncSetAttribute(edge_kernel,
                             cudaFuncAttributeMaxDynamicSharedMemorySize, SMEM_BYTES);
        smem_set = 1;
    }

    zero_agg_kernel<<<(NNODES * HID / 4 + 255) / 256, 256>>>();

    edge_kernel<<<EDGE_BLOCKS, 256, SMEM_BYTES>>>(
        pos, ei, rbf_c, rbf_w, sh_w, sh_b, pm_w1, pm_b1, pm_w2, pm_b2);

    node_kernel<<<NNODES / 8, 256>>>(
        pos, zinc, rbf_c, rbf_w, sh_w, sh_b, zn_w, zn_b, np_w, np_b,
        ln_g, ln_b, out);
}

// round 9
// speedup vs baseline: 2.6586x; 1.2201x over previous
#include <cuda_runtime.h>
#include <cuda_bf16.h>
#include <math.h>
#include <stdint.h>

#define NNODES 100000
#define NEDGES 1600000
#define NB 16
#define HID 64
#define OUTD 128
#define NCHUNKS (NEDGES / 32)    // 50000 edge warp-chunks
#define EDGE_BLOCKS 148
#define NODE_CHUNKS (NNODES / 32) // 3125
#define NODE_NW 4                 // warps per node block
#define NODE_BLOCKS ((NODE_CHUNKS + NODE_NW - 1) / NODE_NW)  // 782

typedef unsigned long long ull;

__device__ float g_agg[(size_t)NNODES * HID];

// ---------------------------------------------------------------------------
// Edge-kernel SMEM layout (bytes)
// ---------------------------------------------------------------------------
#define OFF_B1V  0
#define OFF_B2V  256
#define OFF_CON  512
#define OFF_W1T  1536
#define OFF_W2T  (OFF_W1T + 64*208)
#define OFF_A1   (OFF_W2T + 64*400)
#define OFF_A2   (OFF_A1 + 256*208)
#define SMEM_BYTES (OFF_A2 + 256*400)   // 196096

// ---------------------------------------------------------------------------
// Node-kernel SMEM layout (bytes)
// ---------------------------------------------------------------------------
#define NOD_NPB  0                              // 128 f32
#define NOD_ZNB  512                            // 64 f32
#define NOD_CON  768                            // 192 f32
#define NOD_ZN   1536                           // 64 x 208B          (W0 stack T)
#define NOD_NP   (NOD_ZN + 64*208)              // 128 x 528B         (np hi|lo T)
#define NOD_A0   (NOD_NP + 128*528)             // NW x 32 x 272B     (zfeat / h0 staging)
#define NOD_X    (NOD_A0 + NODE_NW*32*272)      // NW x 32 x 528B     (Xh|Xl)
#define NOD_SMEM (NOD_X + NODE_NW*32*528)       // 184832

// ---------------------------------------------------------------------------
// helpers
// ---------------------------------------------------------------------------
__device__ __forceinline__ float silu_f(float x) {
    return __fdividef(x, 1.0f + __expf(-x));
}
__device__ __forceinline__ float trunc_hi(float x) {
    return __uint_as_float(__float_as_uint(x) & 0xFFFF0000u);
}
__device__ __forceinline__ unsigned short hi16(float x) {
    return (unsigned short)(__float_as_uint(x) >> 16);
}
__device__ __forceinline__ unsigned short lo_bf16(float x) {
    return __bfloat16_as_ushort(__float2bfloat16_rn(x - trunc_hi(x)));
}
__device__ __forceinline__ uint32_t pack_hi2(float a, float b) {
    uint32_t r;
    asm("prmt.b32 %0, %1, %2, 0x7632;"
        : "=r"(r) : "r"(__float_as_uint(a)), "r"(__float_as_uint(b)));
    return r;
}
__device__ __forceinline__ uint32_t pack_lo2(float a, float b) {
    float la = a - trunc_hi(a), lb = b - trunc_hi(b);
    uint32_t r;
    asm("cvt.rn.bf16x2.f32 %0, %1, %2;" : "=r"(r) : "f"(lb), "f"(la));
    return r;
}
__device__ __forceinline__ void mma16816(float& d0, float& d1, float& d2, float& d3,
                                         uint32_t a0, uint32_t a1, uint32_t a2, uint32_t a3,
                                         uint32_t b0, uint32_t b1) {
    asm volatile(
        "mma.sync.aligned.m16n8k16.row.col.f32.bf16.bf16.f32 "
        "{%0,%1,%2,%3}, {%4,%5,%6,%7}, {%8,%9}, {%0,%1,%2,%3};"
        : "+f"(d0), "+f"(d1), "+f"(d2), "+f"(d3)
        : "r"(a0), "r"(a1), "r"(a2), "r"(a3), "r"(b0), "r"(b1));
}

#define SH_C0 0.28209479177387814f
#define SH_C1 0.4886025119029199f
#define SH_C2 1.0925484305920792f
#define SH_C3 0.31539156525252005f
#define SH_C4 0.5462742152960396f

// builds 32-dim feature from (dist, ux, uy, uz) using staged constants
__device__ __forceinline__ void build_feat32(
    float dist, float ux, float uy, float uz,
    const float* s_c, const float* s_wd, const float* s_shb, const float* s_shw,
    float feat[32])
{
#pragma unroll
    for (int k = 0; k < NB; k++) {
        const float tt = dist - s_c[k];
        feat[k] = __expf(-fabsf(s_wd[k]) * tt * tt);
    }
    float sh[9];
    sh[0] = SH_C0;
    sh[1] = SH_C1 * uy;
    sh[2] = SH_C1 * uz;
    sh[3] = SH_C1 * ux;
    sh[4] = SH_C2 * ux * uy;
    sh[5] = SH_C2 * uy * uz;
    sh[6] = SH_C3 * (2.0f * uz * uz - ux * ux - uy * uy);
    sh[7] = SH_C2 * ux * uz;
    sh[8] = SH_C4 * (ux * ux - uy * uy);
#pragma unroll
    for (int k = 0; k < NB; k++) {
        float a = s_shb[k];
#pragma unroll
        for (int j = 0; j < 9; j++) a += sh[j] * s_shw[j * NB + k];
        feat[NB + k] = a;
    }
}

// write feature row as [Fh(32) | Fh(32) | Fl(32)] bf16 at `row` (any stride base)
__device__ __forceinline__ void write_split_row96(char* row, const float feat[32]) {
#pragma unroll
    for (int c = 0; c < 4; c++) {
        uint4 hi, lo;
        hi.x = pack_hi2(feat[8 * c + 0], feat[8 * c + 1]);
        hi.y = pack_hi2(feat[8 * c + 2], feat[8 * c + 3]);
        hi.z = pack_hi2(feat[8 * c + 4], feat[8 * c + 5]);
        hi.w = pack_hi2(feat[8 * c + 6], feat[8 * c + 7]);
        lo.x = pack_lo2(feat[8 * c + 0], feat[8 * c + 1]);
        lo.y = pack_lo2(feat[8 * c + 2], feat[8 * c + 3]);
        lo.z = pack_lo2(feat[8 * c + 4], feat[8 * c + 5]);
        lo.w = pack_lo2(feat[8 * c + 6], feat[8 * c + 7]);
        *reinterpret_cast<uint4*>(row + c * 16)       = hi;
        *reinterpret_cast<uint4*>(row + 64 + c * 16)  = hi;
        *reinterpret_cast<uint4*>(row + 128 + c * 16) = lo;
    }
}

// ---------------------------------------------------------------------------
__global__ void zero_agg_kernel() {
    size_t i = (size_t)blockIdx.x * blockDim.x + threadIdx.x;
    size_t n4 = (size_t)NNODES * HID / 4;
    if (i < n4) reinterpret_cast<float4*>(g_agg)[i] = make_float4(0.f, 0.f, 0.f, 0.f);
}

// ---------------------------------------------------------------------------
// Edge kernel: warp-per-32-edges, mma.sync bf16 3-term split GEMMs. (proven)
// ---------------------------------------------------------------------------
__global__ __launch_bounds__(256) void edge_kernel(
    const float* __restrict__ pos,
    const int*   __restrict__ ei,
    const float* __restrict__ rbf_c,
    const float* __restrict__ rbf_w,
    const float* __restrict__ sh_w,
    const float* __restrict__ sh_b,
    const float* __restrict__ w1,
    const float* __restrict__ b1,
    const float* __restrict__ w2,
    const float* __restrict__ b2)
{
    extern __shared__ char smem[];
    const int tid = threadIdx.x;
    const int wid = tid >> 5;
    const int lane = tid & 31;

    for (int i = tid; i < 64 * 96; i += 256) {
        const int n = i / 96, k = i % 96;
        unsigned short v;
        if (k < 32)      v = hi16(w1[k * HID + n]);
        else if (k < 64) v = lo_bf16(w1[(k - 32) * HID + n]);
        else             v = hi16(w1[(k - 64) * HID + n]);
        *reinterpret_cast<unsigned short*>(smem + OFF_W1T + n * 208 + k * 2) = v;
    }
    for (int i = tid; i < 64 * 192; i += 256) {
        const int n = i / 192, k = i % 192;
        unsigned short v;
        if (k < 64)       v = hi16(w2[k * HID + n]);
        else if (k < 128) v = lo_bf16(w2[(k - 64) * HID + n]);
        else              v = hi16(w2[(k - 128) * HID + n]);
        *reinterpret_cast<unsigned short*>(smem + OFF_W2T + n * 400 + k * 2) = v;
    }
    float* s_b1v = reinterpret_cast<float*>(smem + OFF_B1V);
    float* s_b2v = reinterpret_cast<float*>(smem + OFF_B2V);
    float* s_con = reinterpret_cast<float*>(smem + OFF_CON);
    if (tid < HID) { s_b1v[tid] = b1[tid]; s_b2v[tid] = b2[tid]; }
    if (tid < NB) {
        s_con[tid]      = rbf_c[tid];
        s_con[16 + tid] = rbf_w[tid];
        s_con[32 + tid] = sh_b[tid];
    }
    for (int i = tid; i < 9 * NB; i += 256) s_con[48 + i] = sh_w[i];
    __syncthreads();

    const float* s_c   = s_con;
    const float* s_wd  = s_con + 16;
    const float* s_shb = s_con + 32;
    const float* s_shw = s_con + 48;

    char* A1w = smem + OFF_A1 + wid * 32 * 208;
    char* A2w = smem + OFF_A2 + wid * 32 * 400;
    char* PFw = A2w;

    const int r0 = lane >> 2;
    const int qp = lane & 3;
    const int xr = (lane >> 3) & 3;

    for (int chunk = blockIdx.x * 8 + wid; chunk < NCHUNKS; chunk += gridDim.x * 8) {
        const int e = chunk * 32 + lane;
        const int s = ei[e];
        const int d = ei[NEDGES + e];

        const float rx = pos[3 * d + 0] - pos[3 * s + 0];
        const float ry = pos[3 * d + 1] - pos[3 * s + 1];
        const float rz = pos[3 * d + 2] - pos[3 * s + 2];
        float dist = fmaxf(sqrtf(rx * rx + ry * ry + rz * rz), 1e-6f);
        const float inv = __fdividef(1.0f, dist);

        float feat[32];
        build_feat32(dist, rx * inv, ry * inv, rz * inv, s_c, s_wd, s_shb, s_shw, feat);
        write_split_row96(A1w + lane * 208, feat);
        __syncwarp();

        float dacc[2][8][4];
#pragma unroll
        for (int mt = 0; mt < 2; mt++)
#pragma unroll
            for (int nt = 0; nt < 8; nt++)
#pragma unroll
                for (int j = 0; j < 4; j++) dacc[mt][nt][j] = 0.0f;

#pragma unroll
        for (int kt = 0; kt < 6; kt++) {
            uint32_t a[2][4];
#pragma unroll
            for (int mt = 0; mt < 2; mt++) {
                const char* base = A1w + (mt * 16 + r0) * 208 + kt * 32 + qp * 4;
                a[mt][0] = *reinterpret_cast<const uint32_t*>(base);
                a[mt][1] = *reinterpret_cast<const uint32_t*>(base + 8 * 208);
                a[mt][2] = *reinterpret_cast<const uint32_t*>(base + 16);
                a[mt][3] = *reinterpret_cast<const uint32_t*>(base + 8 * 208 + 16);
            }
#pragma unroll
            for (int nt = 0; nt < 8; nt++) {
                const char* bb = smem + OFF_W1T + (nt * 8 + r0) * 208 + kt * 32 + qp * 4;
                const uint32_t b0 = *reinterpret_cast<const uint32_t*>(bb);
                const uint32_t bb1 = *reinterpret_cast<const uint32_t*>(bb + 16);
                mma16816(dacc[0][nt][0], dacc[0][nt][1], dacc[0][nt][2], dacc[0][nt][3],
                         a[0][0], a[0][1], a[0][2], a[0][3], b0, bb1);
                mma16816(dacc[1][nt][0], dacc[1][nt][1], dacc[1][nt][2], dacc[1][nt][3],
                         a[1][0], a[1][1], a[1][2], a[1][3], b0, bb1);
            }
        }

#pragma unroll
        for (int nt = 0; nt < 8; nt++) {
            const float2 bp = *reinterpret_cast<const float2*>(s_b1v + nt * 8 + 2 * qp);
#pragma unroll
            for (int mt = 0; mt < 2; mt++) {
#pragma unroll
                for (int sdx = 0; sdx < 2; sdx++) {
                    const float p0 = silu_f(dacc[mt][nt][2 * sdx + 0] + bp.x);
                    const float p1 = silu_f(dacc[mt][nt][2 * sdx + 1] + bp.y);
                    const int rloc = mt * 16 + sdx * 8 + r0;
                    char* prow = A2w + rloc * 400;
                    const int cb = nt * 16 + qp * 4;
                    const uint32_t hi = pack_hi2(p0, p1);
                    const uint32_t lo = pack_lo2(p0, p1);
                    *reinterpret_cast<uint32_t*>(prow + cb)       = hi;
                    *reinterpret_cast<uint32_t*>(prow + 128 + cb) = hi;
                    *reinterpret_cast<uint32_t*>(prow + 256 + cb) = lo;
                }
            }
        }
        __syncwarp();

#pragma unroll
        for (int mt = 0; mt < 2; mt++)
#pragma unroll
            for (int nt = 0; nt < 8; nt++)
#pragma unroll
                for (int j = 0; j < 4; j++) dacc[mt][nt][j] = 0.0f;

#pragma unroll 4
        for (int kt = 0; kt < 12; kt++) {
            uint32_t a[2][4];
#pragma unroll
            for (int mt = 0; mt < 2; mt++) {
                const char* base = A2w + (mt * 16 + r0) * 400 + kt * 32 + qp * 4;
                a[mt][0] = *reinterpret_cast<const uint32_t*>(base);
                a[mt][1] = *reinterpret_cast<const uint32_t*>(base + 8 * 400);
                a[mt][2] = *reinterpret_cast<const uint32_t*>(base + 16);
                a[mt][3] = *reinterpret_cast<const uint32_t*>(base + 8 * 400 + 16);
            }
#pragma unroll
            for (int nt = 0; nt < 8; nt++) {
                const char* bb = smem + OFF_W2T + (nt * 8 + r0) * 400 + kt * 32 + qp * 4;
                const uint32_t b0 = *reinterpret_cast<const uint32_t*>(bb);
                const uint32_t bb1 = *reinterpret_cast<const uint32_t*>(bb + 16);
                mma16816(dacc[0][nt][0], dacc[0][nt][1], dacc[0][nt][2], dacc[0][nt][3],
                         a[0][0], a[0][1], a[0][2], a[0][3], b0, bb1);
                mma16816(dacc[1][nt][0], dacc[1][nt][1], dacc[1][nt][2], dacc[1][nt][3],
                         a[1][0], a[1][1], a[1][2], a[1][3], b0, bb1);
            }
        }
        __syncwarp();

#pragma unroll
        for (int nt = 0; nt < 8; nt++) {
            const float2 bp = *reinterpret_cast<const float2*>(s_b2v + nt * 8 + 2 * qp);
            const int g = (qp >> 1) + 2 * nt;
            const int gsub = (qp & 1) << 3;
#pragma unroll
            for (int mt = 0; mt < 2; mt++) {
#pragma unroll
                for (int sdx = 0; sdx < 2; sdx++) {
                    const int rloc = mt * 16 + sdx * 8 + r0;
                    float2 v;
                    v.x = dacc[mt][nt][2 * sdx + 0] + bp.x;
                    v.y = dacc[mt][nt][2 * sdx + 1] + bp.y;
                    const int gs = g ^ ((rloc >> 3) & 3);
                    *reinterpret_cast<float2*>(PFw + rloc * 272 + gs * 16 + gsub) = v;
                }
            }
        }
        __syncwarp();

        {
            const char* myrow = PFw + lane * 272;
            float* ap = g_agg + (size_t)s * HID;
#pragma unroll
            for (int i = 0; i < 16; i++) {
                const float4 v = *reinterpret_cast<const float4*>(myrow + ((i ^ xr) << 4));
                asm volatile("red.global.add.v4.f32 [%0], {%1, %2, %3, %4};"
                             :: "l"(ap + 4 * i), "f"(v.x), "f"(v.y), "f"(v.z), "f"(v.w)
                             : "memory");
            }
        }
        __syncwarp();
    }
}

// ---------------------------------------------------------------------------
// Node kernel: warp-per-32-nodes, mma.sync split GEMMs + fragment LayerNorm.
// ---------------------------------------------------------------------------
__global__ __launch_bounds__(128) void node_kernel(
    const float* __restrict__ pos,
    const float* __restrict__ zinc,
    const float* __restrict__ rbf_c,
    const float* __restrict__ rbf_w,
    const float* __restrict__ sh_w,
    const float* __restrict__ sh_b,
    const float* __restrict__ zn_w,   // [32,64]
    const float* __restrict__ zn_b,
    const float* __restrict__ np_w,   // [128,128]
    const float* __restrict__ np_b,
    const float* __restrict__ ln_g,
    const float* __restrict__ ln_b,
    float* __restrict__ out)
{
    extern __shared__ char smem[];
    const int tid = threadIdx.x;
    const int wid = tid >> 5;
    const int lane = tid & 31;

    // ---- stage weights ----
    for (int i = tid; i < 64 * 96; i += 128) {
        const int n = i / 96, k = i % 96;
        unsigned short v;
        if (k < 32)      v = hi16(zn_w[k * HID + n]);
        else if (k < 64) v = lo_bf16(zn_w[(k - 32) * HID + n]);
        else             v = hi16(zn_w[(k - 64) * HID + n]);
        *reinterpret_cast<unsigned short*>(smem + NOD_ZN + n * 208 + k * 2) = v;
    }
    // np: coalesced over n (inner dim of np_w row)
    for (int i = tid; i < 128 * 128; i += 128) {
        const int k = i >> 7, n = i & 127;
        const float w = np_w[k * OUTD + n];
        *reinterpret_cast<unsigned short*>(smem + NOD_NP + n * 528 + k * 2)       = hi16(w);
        *reinterpret_cast<unsigned short*>(smem + NOD_NP + n * 528 + 256 + k * 2) = lo_bf16(w);
    }
    float* s_npb = reinterpret_cast<float*>(smem + NOD_NPB);
    float* s_znb = reinterpret_cast<float*>(smem + NOD_ZNB);
    float* s_con = reinterpret_cast<float*>(smem + NOD_CON);
    if (tid < OUTD) s_npb[tid] = np_b[tid];
    if (tid < HID)  s_znb[tid] = zn_b[tid];
    if (tid < NB) {
        s_con[tid]      = rbf_c[tid];
        s_con[16 + tid] = rbf_w[tid];
        s_con[32 + tid] = sh_b[tid];
    }
    for (int i = tid; i < 9 * NB; i += 128) s_con[48 + i] = sh_w[i];
    __syncthreads();

    const int chunk = blockIdx.x * NODE_NW + wid;
    if (chunk >= NODE_CHUNKS) return;

    const float* s_c   = s_con;
    const float* s_wd  = s_con + 16;
    const float* s_shb = s_con + 32;
    const float* s_shw = s_con + 48;

    char* A0w = smem + NOD_A0 + wid * 32 * 272;
    char* Xw  = smem + NOD_X  + wid * 32 * 528;

    const int r0 = lane >> 2;
    const int qp = lane & 3;
    const int node = chunk * 32 + lane;

    // ---- zinc features (scalar, per lane = per node) ----
    {
        const float rx = pos[3 * node + 0] - __ldg(&zinc[0]);
        const float ry = pos[3 * node + 1] - __ldg(&zinc[1]);
        const float rz = pos[3 * node + 2] - __ldg(&zinc[2]);
        float dist = fmaxf(sqrtf(rx * rx + ry * ry + rz * rz), 1e-6f);
        const float inv = __fdividef(1.0f, dist);
        float feat[32];
        build_feat32(dist, rx * inv, ry * inv, rz * inv, s_c, s_wd, s_shb, s_shw, feat);
        write_split_row96(A0w + lane * 272, feat);
    }

    // ---- load agg rows into X cols 0..63 (hi/lo) ----
    {
        const float* ab = g_agg + (size_t)(chunk * 32) * HID;
        const int f = lane & 15;
#pragma unroll
        for (int i = 0; i < 16; i++) {
            const int r = i * 2 + (lane >> 4);
            const float4 v = *reinterpret_cast<const float4*>(ab + r * HID + f * 4);
            uint2 hi, lo;
            hi.x = pack_hi2(v.x, v.y); hi.y = pack_hi2(v.z, v.w);
            lo.x = pack_lo2(v.x, v.y); lo.y = pack_lo2(v.z, v.w);
            *reinterpret_cast<uint2*>(Xw + r * 528 + f * 8)       = hi;
            *reinterpret_cast<uint2*>(Xw + r * 528 + 256 + f * 8) = lo;
        }
    }
    __syncwarp();

    // ---- GEMM0: zfeat[32x96] @ ZN[96x64] ----
    {
        float dz[2][8][4];
#pragma unroll
        for (int mt = 0; mt < 2; mt++)
#pragma unroll
            for (int nt = 0; nt < 8; nt++)
#pragma unroll
                for (int j = 0; j < 4; j++) dz[mt][nt][j] = 0.0f;

#pragma unroll
        for (int kt = 0; kt < 6; kt++) {
            uint32_t a[2][4];
#pragma unroll
            for (int mt = 0; mt < 2; mt++) {
                const char* base = A0w + (mt * 16 + r0) * 272 + kt * 32 + qp * 4;
                a[mt][0] = *reinterpret_cast<const uint32_t*>(base);
                a[mt][1] = *reinterpret_cast<const uint32_t*>(base + 8 * 272);
                a[mt][2] = *reinterpret_cast<const uint32_t*>(base + 16);
                a[mt][3] = *reinterpret_cast<const uint32_t*>(base + 8 * 272 + 16);
            }
#pragma unroll
            for (int nt = 0; nt < 8; nt++) {
                const char* bb = smem + NOD_ZN + (nt * 8 + r0) * 208 + kt * 32 + qp * 4;
                const uint32_t b0 = *reinterpret_cast<const uint32_t*>(bb);
                const uint32_t bb1 = *reinterpret_cast<const uint32_t*>(bb + 16);
                mma16816(dz[0][nt][0], dz[0][nt][1], dz[0][nt][2], dz[0][nt][3],
                         a[0][0], a[0][1], a[0][2], a[0][3], b0, bb1);
                mma16816(dz[1][nt][0], dz[1][nt][1], dz[1][nt][2], dz[1][nt][3],
                         a[1][0], a[1][1], a[1][2], a[1][3], b0, bb1);
            }
        }

        // epilogue0: bias + silu -> X cols 64..127 (hi/lo)
#pragma unroll
        for (int nt = 0; nt < 8; nt++) {
            const float2 bp = *reinterpret_cast<const float2*>(s_znb + nt * 8 + 2 * qp);
#pragma unroll
            for (int mt = 0; mt < 2; mt++) {
#pragma unroll
                for (int sdx = 0; sdx < 2; sdx++) {
                    const float p0 = silu_f(dz[mt][nt][2 * sdx + 0] + bp.x);
                    const float p1 = silu_f(dz[mt][nt][2 * sdx + 1] + bp.y);
                    const int rloc = mt * 16 + sdx * 8 + r0;
                    const int c = nt * 8 + qp * 2;      // 0..63 local
                    *reinterpret_cast<uint32_t*>(Xw + rloc * 528 + 128 + c * 2) =
                        pack_hi2(p0, p1);
                    *reinterpret_cast<uint32_t*>(Xw + rloc * 528 + 384 + c * 2) =
                        pack_lo2(p0, p1);
                }
            }
        }
    }
    __syncwarp();

    // ---- main GEMM: X[32x128] @ NP[128x128], two N-halves, 3 split passes ----
    float dacc[2][8][4];
    float sum[4], sq[4], mu[4], rs[4];

#pragma unroll
    for (int half = 0; half < 2; half++) {
#pragma unroll
        for (int mt = 0; mt < 2; mt++)
#pragma unroll
            for (int nt = 0; nt < 8; nt++)
#pragma unroll
                for (int j = 0; j < 4; j++) dacc[mt][nt][j] = 0.0f;

#pragma unroll
        for (int pass = 0; pass < 3; pass++) {
            const int aoff = (pass == 2) ? 256 : 0;
            const int boff = (pass == 1) ? 256 : 0;
#pragma unroll
            for (int kt = 0; kt < 8; kt++) {
                uint32_t a[2][4];
#pragma unroll
                for (int mt = 0; mt < 2; mt++) {
                    const char* base = Xw + (mt * 16 + r0) * 528 + aoff + kt * 32 + qp * 4;
                    a[mt][0] = *reinterpret_cast<const uint32_t*>(base);
                    a[mt][1] = *reinterpret_cast<const uint32_t*>(base + 8 * 528);
                    a[mt][2] = *reinterpret_cast<const uint32_t*>(base + 16);
                    a[mt][3] = *reinterpret_cast<const uint32_t*>(base + 8 * 528 + 16);
                }
#pragma unroll
                for (int nt = 0; nt < 8; nt++) {
                    const char* bb = smem + NOD_NP +
                        (half * 64 + nt * 8 + r0) * 528 + boff + kt * 32 + qp * 4;
                    const uint32_t b0 = *reinterpret_cast<const uint32_t*>(bb);
                    const uint32_t bb1 = *reinterpret_cast<const uint32_t*>(bb + 16);
                    mma16816(dacc[0][nt][0], dacc[0][nt][1], dacc[0][nt][2], dacc[0][nt][3],
                             a[0][0], a[0][1], a[0][2], a[0][3], b0, bb1);
                    mma16816(dacc[1][nt][0], dacc[1][nt][1], dacc[1][nt][2], dacc[1][nt][3],
                             a[1][0], a[1][1], a[1][2], a[1][3], b0, bb1);
                }
            }
        }

        if (half == 0) {
            // stage h(cols 0..63) = dacc + np_b into A0 region (f32)
            __syncwarp();   // GEMM0 A no longer needed; reuse A0w
#pragma unroll
            for (int nt = 0; nt < 8; nt++) {
                const float2 bp = *reinterpret_cast<const float2*>(s_npb + nt * 8 + 2 * qp);
#pragma unroll
                for (int mt = 0; mt < 2; mt++) {
#pragma unroll
                    for (int sdx = 0; sdx < 2; sdx++) {
                        const int rloc = mt * 16 + sdx * 8 + r0;
                        const int c = nt * 8 + qp * 2;
                        float2 v;
                        v.x = dacc[mt][nt][2 * sdx + 0] + bp.x;
                        v.y = dacc[mt][nt][2 * sdx + 1] + bp.y;
                        *reinterpret_cast<float2*>(A0w + rloc * 272 + c * 4) = v;
                    }
                }
            }
            __syncwarp();
        }
    }

    // half1 bias
#pragma unroll
    for (int nt = 0; nt < 8; nt++) {
        const float2 bp = *reinterpret_cast<const float2*>(s_npb + 64 + nt * 8 + 2 * qp);
#pragma unroll
        for (int mt = 0; mt < 2; mt++) {
#pragma unroll
            for (int sdx = 0; sdx < 2; sdx++) {
                dacc[mt][nt][2 * sdx + 0] += bp.x;
                dacc[mt][nt][2 * sdx + 1] += bp.y;
            }
        }
    }

    // ---- LayerNorm stats: per-row sum over 4 qp-lanes ----
#pragma unroll
    for (int j = 0; j < 4; j++) sum[j] = 0.0f;
#pragma unroll
    for (int nt = 0; nt < 8; nt++) {
#pragma unroll
        for (int mt = 0; mt < 2; mt++) {
#pragma unroll
            for (int sdx = 0; sdx < 2; sdx++) {
                const int j = mt * 2 + sdx;
                const int rloc = mt * 16 + sdx * 8 + r0;
                const float2 h0 = *reinterpret_cast<const float2*>(
                    A0w + rloc * 272 + (nt * 8 + qp * 2) * 4);
                sum[j] += h0.x + h0.y + dacc[mt][nt][2 * sdx] + dacc[mt][nt][2 * sdx + 1];
            }
        }
    }
#pragma unroll
    for (int j = 0; j < 4; j++) {
        sum[j] += __shfl_xor_sync(0xffffffffu, sum[j], 1);
        sum[j] += __shfl_xor_sync(0xffffffffu, sum[j], 2);
        mu[j] = sum[j] * (1.0f / 128.0f);
        sq[j] = 0.0f;
    }
#pragma unroll
    for (int nt = 0; nt < 8; nt++) {
#pragma unroll
        for (int mt = 0; mt < 2; mt++) {
#pragma unroll
            for (int sdx = 0; sdx < 2; sdx++) {
                const int j = mt * 2 + sdx;
                const int rloc = mt * 16 + sdx * 8 + r0;
                const float2 h0 = *reinterpret_cast<const float2*>(
                    A0w + rloc * 272 + (nt * 8 + qp * 2) * 4);
                const float d0 = h0.x - mu[j], d1 = h0.y - mu[j];
                const float d2 = dacc[mt][nt][2 * sdx] - mu[j];
                const float d3 = dacc[mt][nt][2 * sdx + 1] - mu[j];
                sq[j] += d0 * d0 + d1 * d1 + d2 * d2 + d3 * d3;
            }
        }
    }
#pragma unroll
    for (int j = 0; j < 4; j++) {
        sq[j] += __shfl_xor_sync(0xffffffffu, sq[j], 1);
        sq[j] += __shfl_xor_sync(0xffffffffu, sq[j], 2);
        rs[j] = rsqrtf(sq[j] * (1.0f / 128.0f) + 1e-5f);
    }

    // ---- output: silu((h-mu)*rs*g + b) ----
#pragma unroll
    for (int nt = 0; nt < 8; nt++) {
        const int c0 = nt * 8 + qp * 2;           // half0 col
        const int c1 = 64 + c0;                   // half1 col
        const float2 g0 = __ldg(reinterpret_cast<const float2*>(ln_g + c0));
        const float2 b0 = __ldg(reinterpret_cast<const float2*>(ln_b + c0));
        const float2 g1 = __ldg(reinterpret_cast<const float2*>(ln_g + c1));
        const float2 b1v = __ldg(reinterpret_cast<const float2*>(ln_b + c1));
#pragma unroll
        for (int mt = 0; mt < 2; mt++) {
#pragma unroll
            for (int sdx = 0; sdx < 2; sdx++) {
                const int j = mt * 2 + sdx;
                const int rloc = mt * 16 + sdx * 8 + r0;
                const size_t orow = (size_t)(chunk * 32 + rloc) * OUTD;
                const float2 h0 = *reinterpret_cast<const float2*>(
                    A0w + rloc * 272 + c0 * 4);
                float2 o0, o1;
                o0.x = silu_f((h0.x - mu[j]) * rs[j] * g0.x + b0.x);
                o0.y = silu_f((h0.y - mu[j]) * rs[j] * g0.y + b0.y);
                o1.x = silu_f((dacc[mt][nt][2 * sdx] - mu[j]) * rs[j] * g1.x + b1v.x);
                o1.y = silu_f((dacc[mt][nt][2 * sdx + 1] - mu[j]) * rs[j] * g1.y + b1v.y);
                *reinterpret_cast<float2*>(out + orow + c0) = o0;
                *reinterpret_cast<float2*>(out + orow + c1) = o1;
            }
        }
    }
}

// ---------------------------------------------------------------------------
extern "C" void kernel_launch(void* const* d_in, const int* in_sizes, int n_in,
                              void* d_out, int out_size) {
    const float* pos    = (const float*)d_in[0];
    const float* zinc   = (const float*)d_in[1];
    const int*   ei     = (const int*)  d_in[2];
    const float* rbf_c  = (const float*)d_in[3];
    const float* rbf_w  = (const float*)d_in[4];
    const float* sh_w   = (const float*)d_in[5];
    const float* sh_b   = (const float*)d_in[6];
    const float* pm_w1  = (const float*)d_in[7];
    const float* pm_b1  = (const float*)d_in[8];
    const float* pm_w2  = (const float*)d_in[9];
    const float* pm_b2  = (const float*)d_in[10];
    const float* zn_w   = (const float*)d_in[11];
    const float* zn_b   = (const float*)d_in[12];
    const float* np_w   = (const float*)d_in[13];
    const float* np_b   = (const float*)d_in[14];
    const float* ln_g   = (const float*)d_in[15];
    const float* ln_b   = (const float*)d_in[16];
    float* out = (float*)d_out;

    static int attr_set = 0;
    if (!attr_set) {
        cudaFuncSetAttribute(edge_kernel,
                             cudaFuncAttributeMaxDynamicSharedMemorySize, SMEM_BYTES);
        cudaFuncSetAttribute(node_kernel,
                             cudaFuncAttributeMaxDynamicSharedMemorySize, NOD_SMEM);
        attr_set = 1;
    }

    zero_agg_kernel<<<(NNODES * HID / 4 + 255) / 256, 256>>>();

    edge_kernel<<<EDGE_BLOCKS, 256, SMEM_BYTES>>>(
        pos, ei, rbf_c, rbf_w, sh_w, sh_b, pm_w1, pm_b1, pm_w2, pm_b2);

    node_kernel<<<NODE_BLOCKS, 128, NOD_SMEM>>>(
        pos, zinc, rbf_c, rbf_w, sh_w, sh_b, zn_w, zn_b, np_w, np_b,
        ln_g, ln_b, out);
}

// round 10
// speedup vs baseline: 3.0949x; 1.1641x over previous
#include <cuda_runtime.h>
#include <cuda_bf16.h>
#include <math.h>
#include <stdint.h>

#define NNODES 100000
#define NEDGES 1600000
#define NB 16
#define HID 64
#define OUTD 128
#define NCHUNKS (NEDGES / 32)     // 50000 edge warp-chunks
#define EDGE_NW 6                 // warps per edge block
#define EDGE_BLOCKS (148 * 2)     // 2 blocks/SM
#define NODE_CHUNKS (NNODES / 32) // 3125
#define NODE_NW 4
#define NODE_BLOCKS ((NODE_CHUNKS + NODE_NW - 1) / NODE_NW)  // 782

typedef unsigned long long ull;

__device__ float g_agg[(size_t)NNODES * HID];

// ---------------------------------------------------------------------------
// Edge-kernel SMEM layout (bytes) — compact 3-pass split operands
// ---------------------------------------------------------------------------
#define OFF_B1V  0                                  // 64 f32
#define OFF_B2V  256                                // 64 f32
#define OFF_CON  512                                // 192 f32 -> ends 1280
#define OFF_W1T  1536                               // 64 x 144B  [W1h|W1l] K=64
#define OFF_W2T  (OFF_W1T + 64*144)                 // 64 x 272B  [W2h|W2l] K=128
#define OFF_A1   (OFF_W2T + 64*272)                 // NW x 32 x 144B  [Fh|Fl]
#define OFF_A2   (OFF_A1 + EDGE_NW*32*144)          // NW x 32 x 272B  [Ph|Pl]
#define SMEM_BYTES (OFF_A2 + EDGE_NW*32*272)        // 108032

// ---------------------------------------------------------------------------
// Node-kernel SMEM layout (unchanged, proven)
// ---------------------------------------------------------------------------
#define NOD_NPB  0
#define NOD_ZNB  512
#define NOD_CON  768
#define NOD_ZN   1536
#define NOD_NP   (NOD_ZN + 64*208)
#define NOD_A0   (NOD_NP + 128*528)
#define NOD_X    (NOD_A0 + NODE_NW*32*272)
#define NOD_SMEM (NOD_X + NODE_NW*32*528)           // 184832

// ---------------------------------------------------------------------------
// helpers
// ---------------------------------------------------------------------------
__device__ __forceinline__ float silu_f(float x) {
    return __fdividef(x, 1.0f + __expf(-x));
}
__device__ __forceinline__ float trunc_hi(float x) {
    return __uint_as_float(__float_as_uint(x) & 0xFFFF0000u);
}
__device__ __forceinline__ unsigned short hi16(float x) {
    return (unsigned short)(__float_as_uint(x) >> 16);
}
__device__ __forceinline__ unsigned short lo_bf16(float x) {
    return __bfloat16_as_ushort(__float2bfloat16_rn(x - trunc_hi(x)));
}
__device__ __forceinline__ uint32_t pack_hi2(float a, float b) {
    uint32_t r;
    asm("prmt.b32 %0, %1, %2, 0x7632;"
        : "=r"(r) : "r"(__float_as_uint(a)), "r"(__float_as_uint(b)));
    return r;
}
__device__ __forceinline__ uint32_t pack_lo2(float a, float b) {
    float la = a - trunc_hi(a), lb = b - trunc_hi(b);
    uint32_t r;
    asm("cvt.rn.bf16x2.f32 %0, %1, %2;" : "=r"(r) : "f"(lb), "f"(la));
    return r;
}
__device__ __forceinline__ void mma16816(float& d0, float& d1, float& d2, float& d3,
                                         uint32_t a0, uint32_t a1, uint32_t a2, uint32_t a3,
                                         uint32_t b0, uint32_t b1) {
    asm volatile(
        "mma.sync.aligned.m16n8k16.row.col.f32.bf16.bf16.f32 "
        "{%0,%1,%2,%3}, {%4,%5,%6,%7}, {%8,%9}, {%0,%1,%2,%3};"
        : "+f"(d0), "+f"(d1), "+f"(d2), "+f"(d3)
        : "r"(a0), "r"(a1), "r"(a2), "r"(a3), "r"(b0), "r"(b1));
}

#define SH_C0 0.28209479177387814f
#define SH_C1 0.4886025119029199f
#define SH_C2 1.0925484305920792f
#define SH_C3 0.31539156525252005f
#define SH_C4 0.5462742152960396f

__device__ __forceinline__ void build_feat32(
    float dist, float ux, float uy, float uz,
    const float* s_c, const float* s_wd, const float* s_shb, const float* s_shw,
    float feat[32])
{
#pragma unroll
    for (int k = 0; k < NB; k++) {
        const float tt = dist - s_c[k];
        feat[k] = __expf(-fabsf(s_wd[k]) * tt * tt);
    }
    float sh[9];
    sh[0] = SH_C0;
    sh[1] = SH_C1 * uy;
    sh[2] = SH_C1 * uz;
    sh[3] = SH_C1 * ux;
    sh[4] = SH_C2 * ux * uy;
    sh[5] = SH_C2 * uy * uz;
    sh[6] = SH_C3 * (2.0f * uz * uz - ux * ux - uy * uy);
    sh[7] = SH_C2 * ux * uz;
    sh[8] = SH_C4 * (ux * ux - uy * uy);
#pragma unroll
    for (int k = 0; k < NB; k++) {
        float a = s_shb[k];
#pragma unroll
        for (int j = 0; j < 9; j++) a += sh[j] * s_shw[j * NB + k];
        feat[NB + k] = a;
    }
}

// write [Fh(64B) | Fl(64B)]
__device__ __forceinline__ void write_split_row64(char* row, const float feat[32]) {
#pragma unroll
    for (int c = 0; c < 4; c++) {
        uint4 hi, lo;
        hi.x = pack_hi2(feat[8 * c + 0], feat[8 * c + 1]);
        hi.y = pack_hi2(feat[8 * c + 2], feat[8 * c + 3]);
        hi.z = pack_hi2(feat[8 * c + 4], feat[8 * c + 5]);
        hi.w = pack_hi2(feat[8 * c + 6], feat[8 * c + 7]);
        lo.x = pack_lo2(feat[8 * c + 0], feat[8 * c + 1]);
        lo.y = pack_lo2(feat[8 * c + 2], feat[8 * c + 3]);
        lo.z = pack_lo2(feat[8 * c + 4], feat[8 * c + 5]);
        lo.w = pack_lo2(feat[8 * c + 6], feat[8 * c + 7]);
        *reinterpret_cast<uint4*>(row + c * 16)      = hi;
        *reinterpret_cast<uint4*>(row + 64 + c * 16) = lo;
    }
}

// for node kernel (unchanged layout: [Fh|Fh|Fl] stride-272 rows)
__device__ __forceinline__ void write_split_row96(char* row, const float feat[32]) {
#pragma unroll
    for (int c = 0; c < 4; c++) {
        uint4 hi, lo;
        hi.x = pack_hi2(feat[8 * c + 0], feat[8 * c + 1]);
        hi.y = pack_hi2(feat[8 * c + 2], feat[8 * c + 3]);
        hi.z = pack_hi2(feat[8 * c + 4], feat[8 * c + 5]);
        hi.w = pack_hi2(feat[8 * c + 6], feat[8 * c + 7]);
        lo.x = pack_lo2(feat[8 * c + 0], feat[8 * c + 1]);
        lo.y = pack_lo2(feat[8 * c + 2], feat[8 * c + 3]);
        lo.z = pack_lo2(feat[8 * c + 4], feat[8 * c + 5]);
        lo.w = pack_lo2(feat[8 * c + 6], feat[8 * c + 7]);
        *reinterpret_cast<uint4*>(row + c * 16)       = hi;
        *reinterpret_cast<uint4*>(row + 64 + c * 16)  = hi;
        *reinterpret_cast<uint4*>(row + 128 + c * 16) = lo;
    }
}

// ---------------------------------------------------------------------------
__global__ void zero_agg_kernel() {
    size_t i = (size_t)blockIdx.x * blockDim.x + threadIdx.x;
    size_t n4 = (size_t)NNODES * HID / 4;
    if (i < n4) reinterpret_cast<float4*>(g_agg)[i] = make_float4(0.f, 0.f, 0.f, 0.f);
}

// ---------------------------------------------------------------------------
// Edge kernel: warp-per-32-edges, 3-pass split GEMMs, compact SMEM (2 blk/SM).
// ---------------------------------------------------------------------------
__global__ __launch_bounds__(32 * EDGE_NW, 2) void edge_kernel(
    const float* __restrict__ pos,
    const int*   __restrict__ ei,
    const float* __restrict__ rbf_c,
    const float* __restrict__ rbf_w,
    const float* __restrict__ sh_w,
    const float* __restrict__ sh_b,
    const float* __restrict__ w1,
    const float* __restrict__ b1,
    const float* __restrict__ w2,
    const float* __restrict__ b2)
{
    extern __shared__ char smem[];
    const int tid = threadIdx.x;
    const int wid = tid >> 5;
    const int lane = tid & 31;
    const int NT = 32 * EDGE_NW;

    // W1 stack: 64 n-rows x [W1h(32) | W1l(32)] K=64, stride 144B
    for (int i = tid; i < 64 * 64; i += NT) {
        const int n = i >> 6, k = i & 63;
        unsigned short v;
        if (k < 32) v = hi16(w1[k * HID + n]);
        else        v = lo_bf16(w1[(k - 32) * HID + n]);
        *reinterpret_cast<unsigned short*>(smem + OFF_W1T + n * 144 + k * 2) = v;
    }
    // W2 stack: 64 n-rows x [W2h(64) | W2l(64)] K=128, stride 272B
    for (int i = tid; i < 64 * 128; i += NT) {
        const int n = i >> 7, k = i & 127;
        unsigned short v;
        if (k < 64) v = hi16(w2[k * HID + n]);
        else        v = lo_bf16(w2[(k - 64) * HID + n]);
        *reinterpret_cast<unsigned short*>(smem + OFF_W2T + n * 272 + k * 2) = v;
    }
    float* s_b1v = reinterpret_cast<float*>(smem + OFF_B1V);
    float* s_b2v = reinterpret_cast<float*>(smem + OFF_B2V);
    float* s_con = reinterpret_cast<float*>(smem + OFF_CON);
    if (tid < HID) { s_b1v[tid] = b1[tid]; s_b2v[tid] = b2[tid]; }
    if (tid < NB) {
        s_con[tid]      = rbf_c[tid];
        s_con[16 + tid] = rbf_w[tid];
        s_con[32 + tid] = sh_b[tid];
    }
    for (int i = tid; i < 9 * NB; i += NT) s_con[48 + i] = sh_w[i];
    __syncthreads();

    const float* s_c   = s_con;
    const float* s_wd  = s_con + 16;
    const float* s_shb = s_con + 32;
    const float* s_shw = s_con + 48;

    char* A1w = smem + OFF_A1 + wid * 32 * 144;
    char* A2w = smem + OFF_A2 + wid * 32 * 272;
    char* PFw = A2w;                 // pf staging reuses A2 slice (stride 272)

    const int r0 = lane >> 2;
    const int qp = lane & 3;
    const int xr = (lane >> 3) & 3;

    for (int chunk = blockIdx.x * EDGE_NW + wid; chunk < NCHUNKS;
         chunk += gridDim.x * EDGE_NW) {
        const int e = chunk * 32 + lane;
        const int s = ei[e];
        const int d = ei[NEDGES + e];

        const float rx = pos[3 * d + 0] - pos[3 * s + 0];
        const float ry = pos[3 * d + 1] - pos[3 * s + 1];
        const float rz = pos[3 * d + 2] - pos[3 * s + 2];
        float dist = fmaxf(sqrtf(rx * rx + ry * ry + rz * rz), 1e-6f);
        const float inv = __fdividef(1.0f, dist);

        float feat[32];
        build_feat32(dist, rx * inv, ry * inv, rz * inv, s_c, s_wd, s_shb, s_shw, feat);
        write_split_row64(A1w + lane * 144, feat);
        __syncwarp();

        float dacc[2][8][4];
#pragma unroll
        for (int mt = 0; mt < 2; mt++)
#pragma unroll
            for (int nt = 0; nt < 8; nt++)
#pragma unroll
                for (int j = 0; j < 4; j++) dacc[mt][nt][j] = 0.0f;

        // ---- GEMM1: 3 passes (Fh@W1h, Fh@W1l, Fl@W1h), 2 kt each ----
#pragma unroll
        for (int pass = 0; pass < 3; pass++) {
            const int aoff = (pass == 2) ? 64 : 0;
            const int boff = (pass == 1) ? 64 : 0;
#pragma unroll
            for (int kt = 0; kt < 2; kt++) {
                uint32_t a[2][4];
#pragma unroll
                for (int mt = 0; mt < 2; mt++) {
                    const char* base = A1w + (mt * 16 + r0) * 144 + aoff + kt * 32 + qp * 4;
                    a[mt][0] = *reinterpret_cast<const uint32_t*>(base);
                    a[mt][1] = *reinterpret_cast<const uint32_t*>(base + 8 * 144);
                    a[mt][2] = *reinterpret_cast<const uint32_t*>(base + 16);
                    a[mt][3] = *reinterpret_cast<const uint32_t*>(base + 8 * 144 + 16);
                }
#pragma unroll
                for (int nt = 0; nt < 8; nt++) {
                    const char* bb = smem + OFF_W1T + (nt * 8 + r0) * 144 + boff + kt * 32 + qp * 4;
                    const uint32_t b0 = *reinterpret_cast<const uint32_t*>(bb);
                    const uint32_t bb1 = *reinterpret_cast<const uint32_t*>(bb + 16);
                    mma16816(dacc[0][nt][0], dacc[0][nt][1], dacc[0][nt][2], dacc[0][nt][3],
                             a[0][0], a[0][1], a[0][2], a[0][3], b0, bb1);
                    mma16816(dacc[1][nt][0], dacc[1][nt][1], dacc[1][nt][2], dacc[1][nt][3],
                             a[1][0], a[1][1], a[1][2], a[1][3], b0, bb1);
                }
            }
        }

        // ---- epilogue1: bias + silu + split -> A2 rows [Ph|Pl] ----
#pragma unroll
        for (int nt = 0; nt < 8; nt++) {
            const float2 bp = *reinterpret_cast<const float2*>(s_b1v + nt * 8 + 2 * qp);
#pragma unroll
            for (int mt = 0; mt < 2; mt++) {
#pragma unroll
                for (int sdx = 0; sdx < 2; sdx++) {
                    const float p0 = silu_f(dacc[mt][nt][2 * sdx + 0] + bp.x);
                    const float p1 = silu_f(dacc[mt][nt][2 * sdx + 1] + bp.y);
                    const int rloc = mt * 16 + sdx * 8 + r0;
                    char* prow = A2w + rloc * 272;
                    const int cb = nt * 16 + qp * 4;
                    *reinterpret_cast<uint32_t*>(prow + cb)       = pack_hi2(p0, p1);
                    *reinterpret_cast<uint32_t*>(prow + 128 + cb) = pack_lo2(p0, p1);
                }
            }
        }
        __syncwarp();

#pragma unroll
        for (int mt = 0; mt < 2; mt++)
#pragma unroll
            for (int nt = 0; nt < 8; nt++)
#pragma unroll
                for (int j = 0; j < 4; j++) dacc[mt][nt][j] = 0.0f;

        // ---- GEMM2: 3 passes (Ph@W2h, Ph@W2l, Pl@W2h), 4 kt each ----
#pragma unroll
        for (int pass = 0; pass < 3; pass++) {
            const int aoff = (pass == 2) ? 128 : 0;
            const int boff = (pass == 1) ? 128 : 0;
#pragma unroll
            for (int kt = 0; kt < 4; kt++) {
                uint32_t a[2][4];
#pragma unroll
                for (int mt = 0; mt < 2; mt++) {
                    const char* base = A2w + (mt * 16 + r0) * 272 + aoff + kt * 32 + qp * 4;
                    a[mt][0] = *reinterpret_cast<const uint32_t*>(base);
                    a[mt][1] = *reinterpret_cast<const uint32_t*>(base + 8 * 272);
                    a[mt][2] = *reinterpret_cast<const uint32_t*>(base + 16);
                    a[mt][3] = *reinterpret_cast<const uint32_t*>(base + 8 * 272 + 16);
                }
#pragma unroll
                for (int nt = 0; nt < 8; nt++) {
                    const char* bb = smem + OFF_W2T + (nt * 8 + r0) * 272 + boff + kt * 32 + qp * 4;
                    const uint32_t b0 = *reinterpret_cast<const uint32_t*>(bb);
                    const uint32_t bb1 = *reinterpret_cast<const uint32_t*>(bb + 16);
                    mma16816(dacc[0][nt][0], dacc[0][nt][1], dacc[0][nt][2], dacc[0][nt][3],
                             a[0][0], a[0][1], a[0][2], a[0][3], b0, bb1);
                    mma16816(dacc[1][nt][0], dacc[1][nt][1], dacc[1][nt][2], dacc[1][nt][3],
                             a[1][0], a[1][1], a[1][2], a[1][3], b0, bb1);
                }
            }
        }
        __syncwarp();

        // ---- epilogue2: bias -> pf staging (swizzled, stride 272) ----
#pragma unroll
        for (int nt = 0; nt < 8; nt++) {
            const float2 bp = *reinterpret_cast<const float2*>(s_b2v + nt * 8 + 2 * qp);
            const int g = (qp >> 1) + 2 * nt;
            const int gsub = (qp & 1) << 3;
#pragma unroll
            for (int mt = 0; mt < 2; mt++) {
#pragma unroll
                for (int sdx = 0; sdx < 2; sdx++) {
                    const int rloc = mt * 16 + sdx * 8 + r0;
                    float2 v;
                    v.x = dacc[mt][nt][2 * sdx + 0] + bp.x;
                    v.y = dacc[mt][nt][2 * sdx + 1] + bp.y;
                    const int gs = g ^ ((rloc >> 3) & 3);
                    *reinterpret_cast<float2*>(PFw + rloc * 272 + gs * 16 + gsub) = v;
                }
            }
        }
        __syncwarp();

        // ---- scatter ----
        {
            const char* myrow = PFw + lane * 272;
            float* ap = g_agg + (size_t)s * HID;
#pragma unroll
            for (int i = 0; i < 16; i++) {
                const float4 v = *reinterpret_cast<const float4*>(myrow + ((i ^ xr) << 4));
                asm volatile("red.global.add.v4.f32 [%0], {%1, %2, %3, %4};"
                             :: "l"(ap + 4 * i), "f"(v.x), "f"(v.y), "f"(v.z), "f"(v.w)
                             : "memory");
            }
        }
        __syncwarp();
    }
}

// ---------------------------------------------------------------------------
// Node kernel: warp-per-32-nodes, mma.sync split GEMMs + fragment LayerNorm.
// (unchanged from R9 — proven at ~90us)
// ---------------------------------------------------------------------------
__global__ __launch_bounds__(128) void node_kernel(
    const float* __restrict__ pos,
    const float* __restrict__ zinc,
    const float* __restrict__ rbf_c,
    const float* __restrict__ rbf_w,
    const float* __restrict__ sh_w,
    const float* __restrict__ sh_b,
    const float* __restrict__ zn_w,
    const float* __restrict__ zn_b,
    const float* __restrict__ np_w,
    const float* __restrict__ np_b,
    const float* __restrict__ ln_g,
    const float* __restrict__ ln_b,
    float* __restrict__ out)
{
    extern __shared__ char smem[];
    const int tid = threadIdx.x;
    const int wid = tid >> 5;
    const int lane = tid & 31;

    for (int i = tid; i < 64 * 96; i += 128) {
        const int n = i / 96, k = i % 96;
        unsigned short v;
        if (k < 32)      v = hi16(zn_w[k * HID + n]);
        else if (k < 64) v = lo_bf16(zn_w[(k - 32) * HID + n]);
        else             v = hi16(zn_w[(k - 64) * HID + n]);
        *reinterpret_cast<unsigned short*>(smem + NOD_ZN + n * 208 + k * 2) = v;
    }
    for (int i = tid; i < 128 * 128; i += 128) {
        const int k = i >> 7, n = i & 127;
        const float w = np_w[k * OUTD + n];
        *reinterpret_cast<unsigned short*>(smem + NOD_NP + n * 528 + k * 2)       = hi16(w);
        *reinterpret_cast<unsigned short*>(smem + NOD_NP + n * 528 + 256 + k * 2) = lo_bf16(w);
    }
    float* s_npb = reinterpret_cast<float*>(smem + NOD_NPB);
    float* s_znb = reinterpret_cast<float*>(smem + NOD_ZNB);
    float* s_con = reinterpret_cast<float*>(smem + NOD_CON);
    if (tid < OUTD) s_npb[tid] = np_b[tid];
    if (tid < HID)  s_znb[tid] = zn_b[tid];
    if (tid < NB) {
        s_con[tid]      = rbf_c[tid];
        s_con[16 + tid] = rbf_w[tid];
        s_con[32 + tid] = sh_b[tid];
    }
    for (int i = tid; i < 9 * NB; i += 128) s_con[48 + i] = sh_w[i];
    __syncthreads();

    const int chunk = blockIdx.x * NODE_NW + wid;
    if (chunk >= NODE_CHUNKS) return;

    const float* s_c   = s_con;
    const float* s_wd  = s_con + 16;
    const float* s_shb = s_con + 32;
    const float* s_shw = s_con + 48;

    char* A0w = smem + NOD_A0 + wid * 32 * 272;
    char* Xw  = smem + NOD_X  + wid * 32 * 528;

    const int r0 = lane >> 2;
    const int qp = lane & 3;
    const int node = chunk * 32 + lane;

    {
        const float rx = pos[3 * node + 0] - __ldg(&zinc[0]);
        const float ry = pos[3 * node + 1] - __ldg(&zinc[1]);
        const float rz = pos[3 * node + 2] - __ldg(&zinc[2]);
        float dist = fmaxf(sqrtf(rx * rx + ry * ry + rz * rz), 1e-6f);
        const float inv = __fdividef(1.0f, dist);
        float feat[32];
        build_feat32(dist, rx * inv, ry * inv, rz * inv, s_c, s_wd, s_shb, s_shw, feat);
        write_split_row96(A0w + lane * 272, feat);
    }

    {
        const float* ab = g_agg + (size_t)(chunk * 32) * HID;
        const int f = lane & 15;
#pragma unroll
        for (int i = 0; i < 16; i++) {
            const int r = i * 2 + (lane >> 4);
            const float4 v = *reinterpret_cast<const float4*>(ab + r * HID + f * 4);
            uint2 hi, lo;
            hi.x = pack_hi2(v.x, v.y); hi.y = pack_hi2(v.z, v.w);
            lo.x = pack_lo2(v.x, v.y); lo.y = pack_lo2(v.z, v.w);
            *reinterpret_cast<uint2*>(Xw + r * 528 + f * 8)       = hi;
            *reinterpret_cast<uint2*>(Xw + r * 528 + 256 + f * 8) = lo;
        }
    }
    __syncwarp();

    {
        float dz[2][8][4];
#pragma unroll
        for (int mt = 0; mt < 2; mt++)
#pragma unroll
            for (int nt = 0; nt < 8; nt++)
#pragma unroll
                for (int j = 0; j < 4; j++) dz[mt][nt][j] = 0.0f;

#pragma unroll
        for (int kt = 0; kt < 6; kt++) {
            uint32_t a[2][4];
#pragma unroll
            for (int mt = 0; mt < 2; mt++) {
                const char* base = A0w + (mt * 16 + r0) * 272 + kt * 32 + qp * 4;
                a[mt][0] = *reinterpret_cast<const uint32_t*>(base);
                a[mt][1] = *reinterpret_cast<const uint32_t*>(base + 8 * 272);
                a[mt][2] = *reinterpret_cast<const uint32_t*>(base + 16);
                a[mt][3] = *reinterpret_cast<const uint32_t*>(base + 8 * 272 + 16);
            }
#pragma unroll
            for (int nt = 0; nt < 8; nt++) {
                const char* bb = smem + NOD_ZN + (nt * 8 + r0) * 208 + kt * 32 + qp * 4;
                const uint32_t b0 = *reinterpret_cast<const uint32_t*>(bb);
                const uint32_t bb1 = *reinterpret_cast<const uint32_t*>(bb + 16);
                mma16816(dz[0][nt][0], dz[0][nt][1], dz[0][nt][2], dz[0][nt][3],
                         a[0][0], a[0][1], a[0][2], a[0][3], b0, bb1);
                mma16816(dz[1][nt][0], dz[1][nt][1], dz[1][nt][2], dz[1][nt][3],
                         a[1][0], a[1][1], a[1][2], a[1][3], b0, bb1);
            }
        }

#pragma unroll
        for (int nt = 0; nt < 8; nt++) {
            const float2 bp = *reinterpret_cast<const float2*>(s_znb + nt * 8 + 2 * qp);
#pragma unroll
            for (int mt = 0; mt < 2; mt++) {
#pragma unroll
                for (int sdx = 0; sdx < 2; sdx++) {
                    const float p0 = silu_f(dz[mt][nt][2 * sdx + 0] + bp.x);
                    const float p1 = silu_f(dz[mt][nt][2 * sdx + 1] + bp.y);
                    const int rloc = mt * 16 + sdx * 8 + r0;
                    const int c = nt * 8 + qp * 2;
                    *reinterpret_cast<uint32_t*>(Xw + rloc * 528 + 128 + c * 2) =
                        pack_hi2(p0, p1);
                    *reinterpret_cast<uint32_t*>(Xw + rloc * 528 + 384 + c * 2) =
                        pack_lo2(p0, p1);
                }
            }
        }
    }
    __syncwarp();

    float dacc[2][8][4];
    float sum[4], sq[4], mu[4], rs[4];

#pragma unroll
    for (int half = 0; half < 2; half++) {
#pragma unroll
        for (int mt = 0; mt < 2; mt++)
#pragma unroll
            for (int nt = 0; nt < 8; nt++)
#pragma unroll
                for (int j = 0; j < 4; j++) dacc[mt][nt][j] = 0.0f;

#pragma unroll
        for (int pass = 0; pass < 3; pass++) {
            const int aoff = (pass == 2) ? 256 : 0;
            const int boff = (pass == 1) ? 256 : 0;
#pragma unroll
            for (int kt = 0; kt < 8; kt++) {
                uint32_t a[2][4];
#pragma unroll
                for (int mt = 0; mt < 2; mt++) {
                    const char* base = Xw + (mt * 16 + r0) * 528 + aoff + kt * 32 + qp * 4;
                    a[mt][0] = *reinterpret_cast<const uint32_t*>(base);
                    a[mt][1] = *reinterpret_cast<const uint32_t*>(base + 8 * 528);
                    a[mt][2] = *reinterpret_cast<const uint32_t*>(base + 16);
                    a[mt][3] = *reinterpret_cast<const uint32_t*>(base + 8 * 528 + 16);
                }
#pragma unroll
                for (int nt = 0; nt < 8; nt++) {
                    const char* bb = smem + NOD_NP +
                        (half * 64 + nt * 8 + r0) * 528 + boff + kt * 32 + qp * 4;
                    const uint32_t b0 = *reinterpret_cast<const uint32_t*>(bb);
                    const uint32_t bb1 = *reinterpret_cast<const uint32_t*>(bb + 16);
                    mma16816(dacc[0][nt][0], dacc[0][nt][1], dacc[0][nt][2], dacc[0][nt][3],
                             a[0][0], a[0][1], a[0][2], a[0][3], b0, bb1);
                    mma16816(dacc[1][nt][0], dacc[1][nt][1], dacc[1][nt][2], dacc[1][nt][3],
                             a[1][0], a[1][1], a[1][2], a[1][3], b0, bb1);
                }
            }
        }

        if (half == 0) {
            __syncwarp();
#pragma unroll
            for (int nt = 0; nt < 8; nt++) {
                const float2 bp = *reinterpret_cast<const float2*>(s_npb + nt * 8 + 2 * qp);
#pragma unroll
                for (int mt = 0; mt < 2; mt++) {
#pragma unroll
                    for (int sdx = 0; sdx < 2; sdx++) {
                        const int rloc = mt * 16 + sdx * 8 + r0;
                        const int c = nt * 8 + qp * 2;
                        float2 v;
                        v.x = dacc[mt][nt][2 * sdx + 0] + bp.x;
                        v.y = dacc[mt][nt][2 * sdx + 1] + bp.y;
                        *reinterpret_cast<float2*>(A0w + rloc * 272 + c * 4) = v;
                    }
                }
            }
            __syncwarp();
        }
    }

#pragma unroll
    for (int nt = 0; nt < 8; nt++) {
        const float2 bp = *reinterpret_cast<const float2*>(s_npb + 64 + nt * 8 + 2 * qp);
#pragma unroll
        for (int mt = 0; mt < 2; mt++) {
#pragma unroll
            for (int sdx = 0; sdx < 2; sdx++) {
                dacc[mt][nt][2 * sdx + 0] += bp.x;
                dacc[mt][nt][2 * sdx + 1] += bp.y;
            }
        }
    }

#pragma unroll
    for (int j = 0; j < 4; j++) sum[j] = 0.0f;
#pragma unroll
    for (int nt = 0; nt < 8; nt++) {
#pragma unroll
        for (int mt = 0; mt < 2; mt++) {
#pragma unroll
            for (int sdx = 0; sdx < 2; sdx++) {
                const int j = mt * 2 + sdx;
                const int rloc = mt * 16 + sdx * 8 + r0;
                const float2 h0 = *reinterpret_cast<const float2*>(
                    A0w + rloc * 272 + (nt * 8 + qp * 2) * 4);
                sum[j] += h0.x + h0.y + dacc[mt][nt][2 * sdx] + dacc[mt][nt][2 * sdx + 1];
            }
        }
    }
#pragma unroll
    for (int j = 0; j < 4; j++) {
        sum[j] += __shfl_xor_sync(0xffffffffu, sum[j], 1);
        sum[j] += __shfl_xor_sync(0xffffffffu, sum[j], 2);
        mu[j] = sum[j] * (1.0f / 128.0f);
        sq[j] = 0.0f;
    }
#pragma unroll
    for (int nt = 0; nt < 8; nt++) {
#pragma unroll
        for (int mt = 0; mt < 2; mt++) {
#pragma unroll
            for (int sdx = 0; sdx < 2; sdx++) {
                const int j = mt * 2 + sdx;
                const int rloc = mt * 16 + sdx * 8 + r0;
                const float2 h0 = *reinterpret_cast<const float2*>(
                    A0w + rloc * 272 + (nt * 8 + qp * 2) * 4);
                const float d0 = h0.x - mu[j], d1 = h0.y - mu[j];
                const float d2 = dacc[mt][nt][2 * sdx] - mu[j];
                const float d3 = dacc[mt][nt][2 * sdx + 1] - mu[j];
                sq[j] += d0 * d0 + d1 * d1 + d2 * d2 + d3 * d3;
            }
        }
    }
#pragma unroll
    for (int j = 0; j < 4; j++) {
        sq[j] += __shfl_xor_sync(0xffffffffu, sq[j], 1);
        sq[j] += __shfl_xor_sync(0xffffffffu, sq[j], 2);
        rs[j] = rsqrtf(sq[j] * (1.0f / 128.0f) + 1e-5f);
    }

#pragma unroll
    for (int nt = 0; nt < 8; nt++) {
        const int c0 = nt * 8 + qp * 2;
        const int c1 = 64 + c0;
        const float2 g0 = __ldg(reinterpret_cast<const float2*>(ln_g + c0));
        const float2 b0 = __ldg(reinterpret_cast<const float2*>(ln_b + c0));
        const float2 g1 = __ldg(reinterpret_cast<const float2*>(ln_g + c1));
        const float2 b1v = __ldg(reinterpret_cast<const float2*>(ln_b + c1));
#pragma unroll
        for (int mt = 0; mt < 2; mt++) {
#pragma unroll
            for (int sdx = 0; sdx < 2; sdx++) {
                const int j = mt * 2 + sdx;
                const int rloc = mt * 16 + sdx * 8 + r0;
                const size_t orow = (size_t)(chunk * 32 + rloc) * OUTD;
                const float2 h0 = *reinterpret_cast<const float2*>(
                    A0w + rloc * 272 + c0 * 4);
                float2 o0, o1;
                o0.x = silu_f((h0.x - mu[j]) * rs[j] * g0.x + b0.x);
                o0.y = silu_f((h0.y - mu[j]) * rs[j] * g0.y + b0.y);
                o1.x = silu_f((dacc[mt][nt][2 * sdx] - mu[j]) * rs[j] * g1.x + b1v.x);
                o1.y = silu_f((dacc[mt][nt][2 * sdx + 1] - mu[j]) * rs[j] * g1.y + b1v.y);
                *reinterpret_cast<float2*>(out + orow + c0) = o0;
                *reinterpret_cast<float2*>(out + orow + c1) = o1;
            }
        }
    }
}

// ---------------------------------------------------------------------------
extern "C" void kernel_launch(void* const* d_in, const int* in_sizes, int n_in,
                              void* d_out, int out_size) {
    const float* pos    = (const float*)d_in[0];
    const float* zinc   = (const float*)d_in[1];
    const int*   ei     = (const int*)  d_in[2];
    const float* rbf_c  = (const float*)d_in[3];
    const float* rbf_w  = (const float*)d_in[4];
    const float* sh_w   = (const float*)d_in[5];
    const float* sh_b   = (const float*)d_in[6];
    const float* pm_w1  = (const float*)d_in[7];
    const float* pm_b1  = (const float*)d_in[8];
    const float* pm_w2  = (const float*)d_in[9];
    const float* pm_b2  = (const float*)d_in[10];
    const float* zn_w   = (const float*)d_in[11];
    const float* zn_b   = (const float*)d_in[12];
    const float* np_w   = (const float*)d_in[13];
    const float* np_b   = (const float*)d_in[14];
    const float* ln_g   = (const float*)d_in[15];
    const float* ln_b   = (const float*)d_in[16];
    float* out = (float*)d_out;

    static int attr_set = 0;
    if (!attr_set) {
        cudaFuncSetAttribute(edge_kernel,
                             cudaFuncAttributeMaxDynamicSharedMemorySize, SMEM_BYTES);
        cudaFuncSetAttribute(node_kernel,
                             cudaFuncAttributeMaxDynamicSharedMemorySize, NOD_SMEM);
        attr_set = 1;
    }

    zero_agg_kernel<<<(NNODES * HID / 4 + 255) / 256, 256>>>();

    edge_kernel<<<EDGE_BLOCKS, 32 * EDGE_NW, SMEM_BYTES>>>(
        pos, ei, rbf_c, rbf_w, sh_w, sh_b, pm_w1, pm_b1, pm_w2, pm_b2);

    node_kernel<<<NODE_BLOCKS, 128, NOD_SMEM>>>(
        pos, zinc, rbf_c, rbf_w, sh_w, sh_b, zn_w, zn_b, np_w, np_b,
        ln_g, ln_b, out);
}